// round 6
// baseline (speedup 1.0000x reference)
#include <cuda_runtime.h>
#include <cuda_bf16.h>
#include <math.h>

// Problem constants
#define Bv 4
#define Lv 2048
#define Dv 1024
#define Hv 16
#define HDv 64
#define Mv (Bv * Lv)          // 8192 rows
#define EPSv 1e-5f

// ---------------- scratch (device globals; no allocs allowed) ----------------
__device__ float g_xt[Mv * Dv];                 // x rounded to tf32
__device__ float g_Wt[4 * Dv * Dv];             // Wq,Wk,Wv,Wo rounded to tf32
__device__ __nv_bfloat16 g_Qh[Bv * Hv * Lv * HDv];  // [B,H,L,HD], pre-scaled
__device__ __nv_bfloat16 g_Kh[Bv * Hv * Lv * HDv];
__device__ __nv_bfloat16 g_Vh[Bv * Hv * Lv * HDv];
__device__ float g_O[Mv * Dv];                  // attention out (tf32-rounded)
__device__ float g_Y[Mv * Dv];                  // pre-LN residual sum

// ---------------- helpers ----------------
__device__ __forceinline__ unsigned f2tf32(float x) {
    unsigned r;
    asm volatile("cvt.rna.tf32.f32 %0, %1;" : "=r"(r) : "f"(x));
    return r;
}

__device__ __forceinline__ float ex2(float x) {
    float y;
    asm("ex2.approx.ftz.f32 %0, %1;" : "=f"(y) : "f"(x));
    return y;
}

__device__ __forceinline__ unsigned smem_u32(const void* p) {
    return (unsigned)__cvta_generic_to_shared(p);
}

__device__ __forceinline__ void cp_async16(unsigned dst, const void* src) {
    asm volatile("cp.async.cg.shared.global [%0], [%1], 16;" :: "r"(dst), "l"(src));
}
__device__ __forceinline__ void cp_commit() {
    asm volatile("cp.async.commit_group;");
}
template<int N> __device__ __forceinline__ void cp_wait() {
    asm volatile("cp.async.wait_group %0;" :: "n"(N));
}

__device__ __forceinline__ void mma16818(float* c, const unsigned* a, const unsigned* b) {
    asm volatile(
        "mma.sync.aligned.m16n8k8.row.col.f32.tf32.tf32.f32 "
        "{%0,%1,%2,%3}, {%4,%5,%6,%7}, {%8,%9}, {%0,%1,%2,%3};"
        : "+f"(c[0]), "+f"(c[1]), "+f"(c[2]), "+f"(c[3])
        : "r"(a[0]), "r"(a[1]), "r"(a[2]), "r"(a[3]), "r"(b[0]), "r"(b[1]));
}

__device__ __forceinline__ void mma_bf16(float* c, unsigned a0, unsigned a1, unsigned a2, unsigned a3,
                                         unsigned b0, unsigned b1) {
    asm volatile(
        "mma.sync.aligned.m16n8k16.row.col.f32.bf16.bf16.f32 "
        "{%0,%1,%2,%3}, {%4,%5,%6,%7}, {%8,%9}, {%0,%1,%2,%3};"
        : "+f"(c[0]), "+f"(c[1]), "+f"(c[2]), "+f"(c[3])
        : "r"(a0), "r"(a1), "r"(a2), "r"(a3), "r"(b0), "r"(b1));
}

__device__ __forceinline__ void ldsm4(unsigned& r0, unsigned& r1, unsigned& r2, unsigned& r3, unsigned addr) {
    asm volatile("ldmatrix.sync.aligned.m8n8.x4.shared.b16 {%0,%1,%2,%3}, [%4];"
                 : "=r"(r0), "=r"(r1), "=r"(r2), "=r"(r3) : "r"(addr));
}
__device__ __forceinline__ void ldsm4t(unsigned& r0, unsigned& r1, unsigned& r2, unsigned& r3, unsigned addr) {
    asm volatile("ldmatrix.sync.aligned.m8n8.x4.trans.shared.b16 {%0,%1,%2,%3}, [%4];"
                 : "=r"(r0), "=r"(r1), "=r"(r2), "=r"(r3) : "r"(addr));
}

// ---------------- pre-pass: round fp32 -> tf32 (rna) ----------------
__global__ __launch_bounds__(256)
void tf32_round_kernel(const float* __restrict__ src, float* __restrict__ dst, int n4)
{
    const int i = blockIdx.x * 256 + threadIdx.x;
    if (i < n4) {
        float4 v = ((const float4*)src)[i];
        v.x = __uint_as_float(f2tf32(v.x));
        v.y = __uint_as_float(f2tf32(v.y));
        v.z = __uint_as_float(f2tf32(v.z));
        v.w = __uint_as_float(f2tf32(v.w));
        ((float4*)dst)[i] = v;
    }
}

// ---------------- tf32 tensor-core GEMM, 4-stage cp.async pipeline ----------------
// mode 0: fused QKV. grid (24, 64). A = g_xt, W = g_Wt[wsel], out bf16 head-split.
// mode 1: Wo.        grid (8, 64).  A = g_O,  W = g_Wt[3], out g_Y fp32 (+residual).
#define GSTAGES 4
#define ASTR 20
#define BSTR 136
#define A_STAGE (128 * ASTR)
#define B_STAGE (16 * BSTR)
#define GEMM_SMEM (GSTAGES * (A_STAGE + B_STAGE) * 4)   // 75776 B

__global__ __launch_bounds__(256, 2)
void gemm_tc_kernel(int mode,
                    const float* __restrict__ bq, const float* __restrict__ bk,
                    const float* __restrict__ bv, const float* __restrict__ bo,
                    const float* __restrict__ xres)
{
    extern __shared__ float gsm[];
    float* sA = gsm;
    float* sB = gsm + GSTAGES * A_STAGE;

    const float* A;
    const float* W;
    const float* bias;
    int wsel, bcol;
    if (mode == 0) {
        wsel = blockIdx.x >> 3;
        bcol = blockIdx.x & 7;
        A = g_xt;
        W = g_Wt + (size_t)wsel * Dv * Dv;
        bias = (wsel == 0) ? bq : ((wsel == 1) ? bk : bv);
    } else {
        wsel = 3;
        bcol = blockIdx.x;
        A = g_O;
        W = g_Wt + (size_t)3 * Dv * Dv;
        bias = bo;
    }

    const int tid  = threadIdx.x;
    const int brow = blockIdx.y;
    const int wid  = tid >> 5;
    const int lane = tid & 31;
    const int wm   = wid & 1;
    const int wn   = wid >> 1;
    const int row4 = lane >> 2;
    const int col  = lane & 3;

    const int ac0_row = tid >> 2,          ac0_kc = (tid & 3) * 4;
    const int ac1_row = (tid + 256) >> 2,  ac1_kc = (tid & 3) * 4;
    const int bc0_row = tid >> 5,          bc0_nc = (tid & 31) * 4;
    const int bc1_row = (tid + 256) >> 5,  bc1_nc = (tid & 31) * 4;

    const float* Agb = A + (size_t)(brow * 128) * Dv;
    const float* Wgb = W + bcol * 128;

    float acc[4][4][4];
#pragma unroll
    for (int i = 0; i < 4; i++)
#pragma unroll
        for (int j = 0; j < 4; j++)
#pragma unroll
            for (int r = 0; r < 4; r++) acc[i][j][r] = 0.f;

    auto copy_stage = [&](int s, int k0) {
        float* as = sA + s * A_STAGE;
        float* bs = sB + s * B_STAGE;
        cp_async16(smem_u32(as + ac0_row * ASTR + ac0_kc),
                   Agb + (size_t)ac0_row * Dv + k0 + ac0_kc);
        cp_async16(smem_u32(as + ac1_row * ASTR + ac1_kc),
                   Agb + (size_t)ac1_row * Dv + k0 + ac1_kc);
        cp_async16(smem_u32(bs + bc0_row * BSTR + bc0_nc),
                   Wgb + (size_t)(k0 + bc0_row) * Dv + bc0_nc);
        cp_async16(smem_u32(bs + bc1_row * BSTR + bc1_nc),
                   Wgb + (size_t)(k0 + bc1_row) * Dv + bc1_nc);
    };

    const int NK = Dv / 16;
#pragma unroll
    for (int s = 0; s < GSTAGES - 1; s++) {
        copy_stage(s, s * 16);
        cp_commit();
    }

    for (int kt = 0; kt < NK; kt++) {
        cp_wait<GSTAGES - 2>();
        __syncthreads();

        const int nxt = kt + GSTAGES - 1;
        if (nxt < NK) copy_stage(nxt & (GSTAGES - 1), nxt * 16);
        cp_commit();

        const unsigned* as = (const unsigned*)(sA + (kt & (GSTAGES - 1)) * A_STAGE);
        const unsigned* bs = (const unsigned*)(sB + (kt & (GSTAGES - 1)) * B_STAGE);

#pragma unroll
        for (int ks = 0; ks < 16; ks += 8) {
            unsigned af[4][4], bf[4][2];
#pragma unroll
            for (int i = 0; i < 4; i++) {
                const int mb = wm * 64 + i * 16 + row4;
                af[i][0] = as[mb * ASTR + ks + col];
                af[i][1] = as[(mb + 8) * ASTR + ks + col];
                af[i][2] = as[mb * ASTR + ks + col + 4];
                af[i][3] = as[(mb + 8) * ASTR + ks + col + 4];
            }
#pragma unroll
            for (int j = 0; j < 4; j++) {
                const int nb = wn * 32 + j * 8 + row4;
                bf[j][0] = bs[(ks + col) * BSTR + nb];
                bf[j][1] = bs[(ks + col + 4) * BSTR + nb];
            }
#pragma unroll
            for (int i = 0; i < 4; i++)
#pragma unroll
                for (int j = 0; j < 4; j++)
                    mma16818(acc[i][j], af[i], bf[j]);
        }
        __syncthreads();
    }

    // epilogue
    const float qsc = 0.125f * 1.4426950408889634f;  // 1/sqrt(64) * log2(e)
#pragma unroll
    for (int i = 0; i < 4; i++) {
#pragma unroll
        for (int j = 0; j < 4; j++) {
            const int m_lo = brow * 128 + wm * 64 + i * 16 + row4;
            const int n0   = bcol * 128 + wn * 32 + j * 8 + col * 2;
#pragma unroll
            for (int half = 0; half < 2; half++) {
                const int m = m_lo + half * 8;
                float v0 = acc[i][j][half * 2 + 0] + bias[n0];
                float v1 = acc[i][j][half * 2 + 1] + bias[n0 + 1];
                if (mode == 1) {
                    v0 += xres[(size_t)m * Dv + n0];
                    v1 += xres[(size_t)m * Dv + n0 + 1];
                    *(float2*)&g_Y[(size_t)m * Dv + n0] = make_float2(v0, v1);
                } else {
                    if (wsel == 0) { v0 *= qsc; v1 *= qsc; }
                    const int b = m >> 11, l = m & 2047;
                    const int h = n0 >> 6, hd = n0 & 63;
                    const size_t idx = ((((size_t)b * Hv + h) * Lv) + l) * HDv + hd;
                    __nv_bfloat16* dst = (wsel == 0) ? g_Qh : ((wsel == 1) ? g_Kh : g_Vh);
                    *(__nv_bfloat162*)&dst[idx] = __float22bfloat162_rn(make_float2(v0, v1));
                }
            }
        }
    }
}

// ---------------- bf16 flash attention: warp M=32, cp.async K/V double buffer ----------------
// 4 warps (128 thr), Br=128, Bc=64; warp w owns q rows [w*32, w*32+32).
// smem bf16, row stride 72 (144B): QP[128][72] (Q then reused as P),
//   2 stages x (K[64][72] + V[64][72]).
#define FQS 72
#define KV_OFF (128 * FQS)             // 9216 elements
#define STG_EL (128 * FQS)             // one stage = K(64*72) + V(64*72) = 9216
#define FLASH_SMEM ((KV_OFF + 2 * STG_EL) * 2)   // 27648 el * 2B = 55296 B

__global__ __launch_bounds__(128, 2)
void flash_tc_kernel()
{
    extern __shared__ __nv_bfloat16 fsm[];
    const unsigned sbase = smem_u32(fsm);

    const int tid  = threadIdx.x;
    const int bh   = blockIdx.y;         // b*16 + h
    const int qb   = blockIdx.x;         // q tile of 128
    const int wid  = tid >> 5;           // 0..3
    const int lane = tid & 31;
    const int g    = lane >> 2;
    const int t    = lane & 3;
    const int qw   = wid * 32;           // warp q-row base (local)

    const __nv_bfloat16* Qg = g_Qh + ((size_t)bh * Lv + qb * 128) * HDv;
    const __nv_bfloat16* Kg = g_Kh + (size_t)bh * Lv * HDv;
    const __nv_bfloat16* Vg = g_Vh + (size_t)bh * Lv * HDv;

    // K/V stage loader: 64 rows x 128B each tensor; thread -> row=tid>>1, half=(tid&1)
    const int kv_row  = tid >> 1;
    const int kv_colb = (tid & 1) * 64;  // byte offset within row
    auto load_kv = [&](int kb, int stg) {
        const __nv_bfloat16* ks = Kg + (size_t)(kb * 64 + kv_row) * HDv + kv_colb / 2;
        const __nv_bfloat16* vs = Vg + (size_t)(kb * 64 + kv_row) * HDv + kv_colb / 2;
        const unsigned kd = sbase + (unsigned)(KV_OFF + stg * STG_EL + kv_row * FQS) * 2 + kv_colb;
        const unsigned vd = kd + 64 * FQS * 2;
#pragma unroll
        for (int i = 0; i < 4; i++) {
            cp_async16(kd + i * 16, ks + i * 8);
            cp_async16(vd + i * 16, vs + i * 8);
        }
    };

    // Q load: thread tid handles row tid (128B = 8 chunks)
    {
        const __nv_bfloat16* qs = Qg + (size_t)tid * HDv;
        const unsigned qd = sbase + (unsigned)(tid * FQS) * 2;
#pragma unroll
        for (int u = 0; u < 8; u++) cp_async16(qd + u * 16, qs + u * 8);
    }
    load_kv(0, 0);
    cp_commit();
    cp_wait<0>();
    __syncthreads();

    // hoist Q fragments: [mfrag][kchunk][4]
    const int a_row = lane & 15;
    const int a_k8  = (lane >> 4) << 3;
    unsigned qf[2][4][4];
#pragma unroll
    for (int mf = 0; mf < 2; mf++) {
        const unsigned base = sbase + (unsigned)((qw + mf * 16 + a_row) * FQS + a_k8) * 2;
#pragma unroll
        for (int kc = 0; kc < 4; kc++)
            ldsm4(qf[mf][kc][0], qf[mf][kc][1], qf[mf][kc][2], qf[mf][kc][3],
                  base + kc * 32);
    }

    // ldmatrix address bases
    const int b_row = ((lane >> 4) << 3) + (lane & 7);
    const int b_k8  = ((lane >> 3) & 1) << 3;
    const int v_row = (((lane >> 3) & 1) << 3) + (lane & 7);
    const int v_col = (lane >> 4) << 3;
    const unsigned pA0 = sbase + (unsigned)((qw + a_row) * FQS + a_k8) * 2;
    const unsigned pA1 = pA0 + 16 * FQS * 2;

    float m[4], l[4];
#pragma unroll
    for (int rs = 0; rs < 4; rs++) { m[rs] = -1e30f; l[rs] = 0.f; }
    float o[2][8][4];
#pragma unroll
    for (int mf = 0; mf < 2; mf++)
#pragma unroll
        for (int j = 0; j < 8; j++)
#pragma unroll
            for (int r = 0; r < 4; r++) o[mf][j][r] = 0.f;

    const int NT = Lv / 64;   // 32
    for (int kb = 0; kb < NT; kb++) {
        const int stg = kb & 1;
        if (kb + 1 < NT) load_kv(kb + 1, stg ^ 1);
        cp_commit();
        cp_wait<1>();
        __syncthreads();

        const unsigned kB = sbase + (unsigned)(KV_OFF + stg * STG_EL + b_row * FQS + b_k8) * 2;
        const unsigned vB = sbase + (unsigned)(KV_OFF + stg * STG_EL + 64 * FQS + v_row * FQS + v_col) * 2;

        // ---- S = Q K^T ----
        float s[2][8][4];
#pragma unroll
        for (int mf = 0; mf < 2; mf++)
#pragma unroll
            for (int j = 0; j < 8; j++)
#pragma unroll
                for (int r = 0; r < 4; r++) s[mf][j][r] = 0.f;

#pragma unroll
        for (int kc = 0; kc < 4; kc++) {
#pragma unroll
            for (int jp = 0; jp < 4; jp++) {
                unsigned b0, b1, b2, b3;
                ldsm4(b0, b1, b2, b3, kB + (unsigned)(jp * 16 * FQS + kc * 16) * 2);
#pragma unroll
                for (int mf = 0; mf < 2; mf++) {
                    mma_bf16(s[mf][2 * jp],     qf[mf][kc][0], qf[mf][kc][1], qf[mf][kc][2], qf[mf][kc][3], b0, b1);
                    mma_bf16(s[mf][2 * jp + 1], qf[mf][kc][0], qf[mf][kc][1], qf[mf][kc][2], qf[mf][kc][3], b2, b3);
                }
            }
        }

        // ---- online softmax (log2 domain) ----
        float rmax[4] = {-1e30f, -1e30f, -1e30f, -1e30f};
#pragma unroll
        for (int mf = 0; mf < 2; mf++)
#pragma unroll
            for (int j = 0; j < 8; j++) {
                rmax[2 * mf]     = fmaxf(rmax[2 * mf],     fmaxf(s[mf][j][0], s[mf][j][1]));
                rmax[2 * mf + 1] = fmaxf(rmax[2 * mf + 1], fmaxf(s[mf][j][2], s[mf][j][3]));
            }
#pragma unroll
        for (int off = 1; off <= 2; off <<= 1)
#pragma unroll
            for (int rs = 0; rs < 4; rs++)
                rmax[rs] = fmaxf(rmax[rs], __shfl_xor_sync(0xffffffffu, rmax[rs], off));

        float mn[4], cr[4], rsum[4];
#pragma unroll
        for (int rs = 0; rs < 4; rs++) {
            mn[rs] = fmaxf(m[rs], rmax[rs]);
            cr[rs] = ex2(m[rs] - mn[rs]);
            rsum[rs] = 0.f;
        }

#pragma unroll
        for (int mf = 0; mf < 2; mf++)
#pragma unroll
            for (int j = 0; j < 8; j++) {
                const float p00 = ex2(s[mf][j][0] - mn[2 * mf]);
                const float p01 = ex2(s[mf][j][1] - mn[2 * mf]);
                const float p10 = ex2(s[mf][j][2] - mn[2 * mf + 1]);
                const float p11 = ex2(s[mf][j][3] - mn[2 * mf + 1]);
                rsum[2 * mf]     += p00 + p01;
                rsum[2 * mf + 1] += p10 + p11;
                *(__nv_bfloat162*)&fsm[(qw + mf * 16 + g) * FQS + j * 8 + 2 * t] =
                    __float22bfloat162_rn(make_float2(p00, p01));
                *(__nv_bfloat162*)&fsm[(qw + mf * 16 + 8 + g) * FQS + j * 8 + 2 * t] =
                    __float22bfloat162_rn(make_float2(p10, p11));
            }
#pragma unroll
        for (int off = 1; off <= 2; off <<= 1)
#pragma unroll
            for (int rs = 0; rs < 4; rs++)
                rsum[rs] += __shfl_xor_sync(0xffffffffu, rsum[rs], off);
#pragma unroll
        for (int rs = 0; rs < 4; rs++) {
            l[rs] = l[rs] * cr[rs] + rsum[rs];
            m[rs] = mn[rs];
        }
#pragma unroll
        for (int mf = 0; mf < 2; mf++)
#pragma unroll
            for (int j = 0; j < 8; j++) {
                o[mf][j][0] *= cr[2 * mf];     o[mf][j][1] *= cr[2 * mf];
                o[mf][j][2] *= cr[2 * mf + 1]; o[mf][j][3] *= cr[2 * mf + 1];
            }
        __syncwarp();

        // ---- O += P V ----
#pragma unroll
        for (int kc = 0; kc < 4; kc++) {
            unsigned pa[2][4];
            ldsm4(pa[0][0], pa[0][1], pa[0][2], pa[0][3], pA0 + kc * 32);
            ldsm4(pa[1][0], pa[1][1], pa[1][2], pa[1][3], pA1 + kc * 32);
#pragma unroll
            for (int jp = 0; jp < 4; jp++) {
                unsigned b0, b1, b2, b3;
                ldsm4t(b0, b1, b2, b3, vB + (unsigned)(kc * 16 * FQS + jp * 16) * 2);
#pragma unroll
                for (int mf = 0; mf < 2; mf++) {
                    mma_bf16(o[mf][2 * jp],     pa[mf][0], pa[mf][1], pa[mf][2], pa[mf][3], b0, b1);
                    mma_bf16(o[mf][2 * jp + 1], pa[mf][0], pa[mf][1], pa[mf][2], pa[mf][3], b2, b3);
                }
            }
        }
        __syncthreads();   // all reads of this stage done before it is overwritten
    }

    // ---- write O to g_O [B,L,D] (tf32-rounded for the Wo GEMM) ----
    const int b = bh >> 4, h = bh & 15;
#pragma unroll
    for (int mf = 0; mf < 2; mf++) {
        const float inv0 = 1.f / l[2 * mf];
        const float inv1 = 1.f / l[2 * mf + 1];
        const int q0 = qb * 128 + qw + mf * 16 + g;
        const int q1 = q0 + 8;
#pragma unroll
        for (int j = 0; j < 8; j++) {
            const int colD = h * HDv + j * 8 + 2 * t;
            float2 w0 = make_float2(__uint_as_float(f2tf32(o[mf][j][0] * inv0)),
                                    __uint_as_float(f2tf32(o[mf][j][1] * inv0)));
            float2 w1 = make_float2(__uint_as_float(f2tf32(o[mf][j][2] * inv1)),
                                    __uint_as_float(f2tf32(o[mf][j][3] * inv1)));
            *(float2*)&g_O[((size_t)b * Lv + q0) * Dv + colD] = w0;
            *(float2*)&g_O[((size_t)b * Lv + q1) * Dv + colD] = w1;
        }
    }
}

// ---------------- LayerNorm: one block per row ----------------
__device__ __forceinline__ float blockReduceSum(float val)
{
    __shared__ float sh[8];
    const int lane = threadIdx.x & 31;
    const int wid  = threadIdx.x >> 5;
#pragma unroll
    for (int o = 16; o > 0; o >>= 1) val += __shfl_xor_sync(0xffffffffu, val, o);
    __syncthreads();
    if (lane == 0) sh[wid] = val;
    __syncthreads();
    if (wid == 0) {
        val = (lane < 8) ? sh[lane] : 0.f;
#pragma unroll
        for (int o = 4; o > 0; o >>= 1) val += __shfl_xor_sync(0xffffffffu, val, o);
        if (lane == 0) sh[0] = val;
    }
    __syncthreads();
    return sh[0];
}

__global__ __launch_bounds__(256)
void layernorm_kernel(const float* __restrict__ gamma,
                      const float* __restrict__ beta,
                      float* __restrict__ out)
{
    const int row = blockIdx.x;
    const int tid = threadIdx.x;
    const float* y = g_Y + (size_t)row * Dv;

    float v[4];
#pragma unroll
    for (int i = 0; i < 4; i++) v[i] = y[tid + i * 256];

    const float total = blockReduceSum(v[0] + v[1] + v[2] + v[3]);
    const float mu = total * (1.f / Dv);

    float d2 = 0.f;
#pragma unroll
    for (int i = 0; i < 4; i++) {
        const float d = v[i] - mu;
        d2 += d * d;
    }
    const float var = blockReduceSum(d2) * (1.f / Dv);
    const float rs = rsqrtf(var + EPSv);

#pragma unroll
    for (int i = 0; i < 4; i++) {
        const int c = tid + i * 256;
        out[(size_t)row * Dv + c] = (v[i] - mu) * rs * gamma[c] + beta[c];
    }
}

// ---------------- launch ----------------
extern "C" void kernel_launch(void* const* d_in, const int* in_sizes, int n_in,
                              void* d_out, int out_size)
{
    (void)in_sizes; (void)n_in; (void)out_size;
    const float* x     = (const float*)d_in[0];
    const float* Wq    = (const float*)d_in[1];
    const float* bq    = (const float*)d_in[2];
    const float* Wk    = (const float*)d_in[3];
    const float* bk    = (const float*)d_in[4];
    const float* Wv    = (const float*)d_in[5];
    const float* bv    = (const float*)d_in[6];
    const float* Wo    = (const float*)d_in[7];
    const float* bo    = (const float*)d_in[8];
    const float* gamma = (const float*)d_in[9];
    const float* beta  = (const float*)d_in[10];
    float* out = (float*)d_out;

    cudaFuncSetAttribute(flash_tc_kernel,
                         cudaFuncAttributeMaxDynamicSharedMemorySize, FLASH_SMEM);
    cudaFuncSetAttribute(gemm_tc_kernel,
                         cudaFuncAttributeMaxDynamicSharedMemorySize, GEMM_SMEM);

    float* d_xt = nullptr;
    float* d_Wt = nullptr;
    cudaGetSymbolAddress((void**)&d_xt, g_xt);
    cudaGetSymbolAddress((void**)&d_Wt, g_Wt);

    // pre-pass: tf32 rounding
    const int nx4 = Mv * Dv / 4;       // 2097152
    const int nw4 = Dv * Dv / 4;       // 262144
    tf32_round_kernel<<<(nx4 + 255) / 256, 256>>>(x, d_xt, nx4);
    tf32_round_kernel<<<(nw4 + 255) / 256, 256>>>(Wq, d_Wt + 0 * Dv * Dv, nw4);
    tf32_round_kernel<<<(nw4 + 255) / 256, 256>>>(Wk, d_Wt + 1 * Dv * Dv, nw4);
    tf32_round_kernel<<<(nw4 + 255) / 256, 256>>>(Wv, d_Wt + 2 * Dv * Dv, nw4);
    tf32_round_kernel<<<(nw4 + 255) / 256, 256>>>(Wo, d_Wt + 3 * Dv * Dv, nw4);

    // fused QKV projection
    gemm_tc_kernel<<<dim3(24, Mv / 128), 256, GEMM_SMEM>>>(0, bq, bk, bv, nullptr, nullptr);

    // attention
    flash_tc_kernel<<<dim3(Lv / 128, Bv * Hv), 128, FLASH_SMEM>>>();

    // output projection + residual
    gemm_tc_kernel<<<dim3(8, Mv / 128), 256, GEMM_SMEM>>>(1, nullptr, nullptr, nullptr, bo, x);

    layernorm_kernel<<<Mv, 256>>>(gamma, beta, out);
}

// round 8
// speedup vs baseline: 1.5068x; 1.5068x over previous
#include <cuda_runtime.h>
#include <cuda_bf16.h>
#include <math.h>

// Problem constants
#define Bv 4
#define Lv 2048
#define Dv 1024
#define Hv 16
#define HDv 64
#define Mv (Bv * Lv)          // 8192 rows
#define EPSv 1e-5f

// ---------------- scratch (device globals; no allocs allowed) ----------------
__device__ float g_xt[Mv * Dv];                 // x rounded to tf32
__device__ float g_Wt[4 * Dv * Dv];             // Wq,Wk,Wv,Wo rounded to tf32
__device__ __nv_bfloat16 g_Qh[Bv * Hv * Lv * HDv];  // [B,H,L,HD], pre-scaled
__device__ __nv_bfloat16 g_Kh[Bv * Hv * Lv * HDv];
__device__ __nv_bfloat16 g_Vh[Bv * Hv * Lv * HDv];
__device__ float g_O[Mv * Dv];                  // attention out (tf32-rounded)
__device__ float g_Y[Mv * Dv];                  // pre-LN residual sum

// ---------------- helpers ----------------
__device__ __forceinline__ unsigned f2tf32(float x) {
    unsigned r;
    asm volatile("cvt.rna.tf32.f32 %0, %1;" : "=r"(r) : "f"(x));
    return r;
}

__device__ __forceinline__ float ex2(float x) {
    float y;
    asm("ex2.approx.ftz.f32 %0, %1;" : "=f"(y) : "f"(x));
    return y;
}

__device__ __forceinline__ unsigned smem_u32(const void* p) {
    return (unsigned)__cvta_generic_to_shared(p);
}

__device__ __forceinline__ void cp_async16(unsigned dst, const void* src) {
    asm volatile("cp.async.cg.shared.global [%0], [%1], 16;" :: "r"(dst), "l"(src));
}
__device__ __forceinline__ void cp_commit() {
    asm volatile("cp.async.commit_group;");
}
template<int N> __device__ __forceinline__ void cp_wait() {
    asm volatile("cp.async.wait_group %0;" :: "n"(N));
}

__device__ __forceinline__ void mma16818(float* c, const unsigned* a, const unsigned* b) {
    asm volatile(
        "mma.sync.aligned.m16n8k8.row.col.f32.tf32.tf32.f32 "
        "{%0,%1,%2,%3}, {%4,%5,%6,%7}, {%8,%9}, {%0,%1,%2,%3};"
        : "+f"(c[0]), "+f"(c[1]), "+f"(c[2]), "+f"(c[3])
        : "r"(a[0]), "r"(a[1]), "r"(a[2]), "r"(a[3]), "r"(b[0]), "r"(b[1]));
}

__device__ __forceinline__ void mma_bf16(float* c, unsigned a0, unsigned a1, unsigned a2, unsigned a3,
                                         unsigned b0, unsigned b1) {
    asm volatile(
        "mma.sync.aligned.m16n8k16.row.col.f32.bf16.bf16.f32 "
        "{%0,%1,%2,%3}, {%4,%5,%6,%7}, {%8,%9}, {%0,%1,%2,%3};"
        : "+f"(c[0]), "+f"(c[1]), "+f"(c[2]), "+f"(c[3])
        : "r"(a0), "r"(a1), "r"(a2), "r"(a3), "r"(b0), "r"(b1));
}

__device__ __forceinline__ void ldsm4(unsigned& r0, unsigned& r1, unsigned& r2, unsigned& r3, unsigned addr) {
    asm volatile("ldmatrix.sync.aligned.m8n8.x4.shared.b16 {%0,%1,%2,%3}, [%4];"
                 : "=r"(r0), "=r"(r1), "=r"(r2), "=r"(r3) : "r"(addr));
}
__device__ __forceinline__ void ldsm4t(unsigned& r0, unsigned& r1, unsigned& r2, unsigned& r3, unsigned addr) {
    asm volatile("ldmatrix.sync.aligned.m8n8.x4.trans.shared.b16 {%0,%1,%2,%3}, [%4];"
                 : "=r"(r0), "=r"(r1), "=r"(r2), "=r"(r3) : "r"(addr));
}

// ---------------- pre-pass: round fp32 -> tf32 (rna) ----------------
__global__ __launch_bounds__(256)
void tf32_round_kernel(const float* __restrict__ src, float* __restrict__ dst, int n4)
{
    const int i = blockIdx.x * 256 + threadIdx.x;
    if (i < n4) {
        float4 v = ((const float4*)src)[i];
        v.x = __uint_as_float(f2tf32(v.x));
        v.y = __uint_as_float(f2tf32(v.y));
        v.z = __uint_as_float(f2tf32(v.z));
        v.w = __uint_as_float(f2tf32(v.w));
        ((float4*)dst)[i] = v;
    }
}

// ---------------- tf32 tensor-core GEMM, 4-stage cp.async pipeline ----------------
// mode 0: fused QKV. grid (24, 64). A = g_xt, W = g_Wt[wsel], out bf16 head-split.
// mode 1: Wo.        grid (8, 64).  A = g_O,  W = g_Wt[3], out g_Y fp32 (+residual).
#define GSTAGES 4
#define ASTR 20
#define BSTR 136
#define A_STAGE (128 * ASTR)
#define B_STAGE (16 * BSTR)
#define GEMM_SMEM (GSTAGES * (A_STAGE + B_STAGE) * 4)   // 75776 B

__global__ __launch_bounds__(256, 2)
void gemm_tc_kernel(int mode,
                    const float* __restrict__ bq, const float* __restrict__ bk,
                    const float* __restrict__ bv, const float* __restrict__ bo,
                    const float* __restrict__ xres)
{
    extern __shared__ float gsm[];
    float* sA = gsm;
    float* sB = gsm + GSTAGES * A_STAGE;

    const float* A;
    const float* W;
    const float* bias;
    int wsel, bcol;
    if (mode == 0) {
        wsel = blockIdx.x >> 3;
        bcol = blockIdx.x & 7;
        A = g_xt;
        W = g_Wt + (size_t)wsel * Dv * Dv;
        bias = (wsel == 0) ? bq : ((wsel == 1) ? bk : bv);
    } else {
        wsel = 3;
        bcol = blockIdx.x;
        A = g_O;
        W = g_Wt + (size_t)3 * Dv * Dv;
        bias = bo;
    }

    const int tid  = threadIdx.x;
    const int brow = blockIdx.y;
    const int wid  = tid >> 5;
    const int lane = tid & 31;
    const int wm   = wid & 1;
    const int wn   = wid >> 1;
    const int row4 = lane >> 2;
    const int col  = lane & 3;

    const int ac0_row = tid >> 2,          ac0_kc = (tid & 3) * 4;
    const int ac1_row = (tid + 256) >> 2,  ac1_kc = (tid & 3) * 4;
    const int bc0_row = tid >> 5,          bc0_nc = (tid & 31) * 4;
    const int bc1_row = (tid + 256) >> 5,  bc1_nc = (tid & 31) * 4;

    const float* Agb = A + (size_t)(brow * 128) * Dv;
    const float* Wgb = W + bcol * 128;

    float acc[4][4][4];
#pragma unroll
    for (int i = 0; i < 4; i++)
#pragma unroll
        for (int j = 0; j < 4; j++)
#pragma unroll
            for (int r = 0; r < 4; r++) acc[i][j][r] = 0.f;

    auto copy_stage = [&](int s, int k0) {
        float* as = sA + s * A_STAGE;
        float* bs = sB + s * B_STAGE;
        cp_async16(smem_u32(as + ac0_row * ASTR + ac0_kc),
                   Agb + (size_t)ac0_row * Dv + k0 + ac0_kc);
        cp_async16(smem_u32(as + ac1_row * ASTR + ac1_kc),
                   Agb + (size_t)ac1_row * Dv + k0 + ac1_kc);
        cp_async16(smem_u32(bs + bc0_row * BSTR + bc0_nc),
                   Wgb + (size_t)(k0 + bc0_row) * Dv + bc0_nc);
        cp_async16(smem_u32(bs + bc1_row * BSTR + bc1_nc),
                   Wgb + (size_t)(k0 + bc1_row) * Dv + bc1_nc);
    };

    const int NK = Dv / 16;
#pragma unroll
    for (int s = 0; s < GSTAGES - 1; s++) {
        copy_stage(s, s * 16);
        cp_commit();
    }

    for (int kt = 0; kt < NK; kt++) {
        cp_wait<GSTAGES - 2>();
        __syncthreads();

        const int nxt = kt + GSTAGES - 1;
        if (nxt < NK) copy_stage(nxt & (GSTAGES - 1), nxt * 16);
        cp_commit();

        const unsigned* as = (const unsigned*)(sA + (kt & (GSTAGES - 1)) * A_STAGE);
        const unsigned* bs = (const unsigned*)(sB + (kt & (GSTAGES - 1)) * B_STAGE);

#pragma unroll
        for (int ks = 0; ks < 16; ks += 8) {
            unsigned af[4][4], bf[4][2];
#pragma unroll
            for (int i = 0; i < 4; i++) {
                const int mb = wm * 64 + i * 16 + row4;
                af[i][0] = as[mb * ASTR + ks + col];
                af[i][1] = as[(mb + 8) * ASTR + ks + col];
                af[i][2] = as[mb * ASTR + ks + col + 4];
                af[i][3] = as[(mb + 8) * ASTR + ks + col + 4];
            }
#pragma unroll
            for (int j = 0; j < 4; j++) {
                const int nb = wn * 32 + j * 8 + row4;
                bf[j][0] = bs[(ks + col) * BSTR + nb];
                bf[j][1] = bs[(ks + col + 4) * BSTR + nb];
            }
#pragma unroll
            for (int i = 0; i < 4; i++)
#pragma unroll
                for (int j = 0; j < 4; j++)
                    mma16818(acc[i][j], af[i], bf[j]);
        }
        __syncthreads();
    }

    // epilogue
    const float qsc = 0.125f * 1.4426950408889634f;  // 1/sqrt(64) * log2(e)
#pragma unroll
    for (int i = 0; i < 4; i++) {
#pragma unroll
        for (int j = 0; j < 4; j++) {
            const int m_lo = brow * 128 + wm * 64 + i * 16 + row4;
            const int n0   = bcol * 128 + wn * 32 + j * 8 + col * 2;
#pragma unroll
            for (int half = 0; half < 2; half++) {
                const int m = m_lo + half * 8;
                float v0 = acc[i][j][half * 2 + 0] + bias[n0];
                float v1 = acc[i][j][half * 2 + 1] + bias[n0 + 1];
                if (mode == 1) {
                    v0 += xres[(size_t)m * Dv + n0];
                    v1 += xres[(size_t)m * Dv + n0 + 1];
                    *(float2*)&g_Y[(size_t)m * Dv + n0] = make_float2(v0, v1);
                } else {
                    if (wsel == 0) { v0 *= qsc; v1 *= qsc; }
                    const int b = m >> 11, l = m & 2047;
                    const int h = n0 >> 6, hd = n0 & 63;
                    const size_t idx = ((((size_t)b * Hv + h) * Lv) + l) * HDv + hd;
                    __nv_bfloat16* dst = (wsel == 0) ? g_Qh : ((wsel == 1) ? g_Kh : g_Vh);
                    *(__nv_bfloat162*)&dst[idx] = __float22bfloat162_rn(make_float2(v0, v1));
                }
            }
        }
    }
}

// ---------------- bf16 flash attention: 256 thr / 8 warps, warp M=16 ----------------
// Br=128, Bc=64. Q hoisted into registers (smem region reused for P).
// K/V double-buffered via cp.async. smem bf16, row stride 72 (144B rows).
#define FQS 72
#define KV_OFF (128 * FQS)             // after QP region (elements)
#define STG_EL (128 * FQS)             // one stage = K[64][72] + V[64][72]
#define FLASH_SMEM ((KV_OFF + 2 * STG_EL) * 2)   // 55296 B

__global__ __launch_bounds__(256, 2)
void flash_tc_kernel()
{
    extern __shared__ __nv_bfloat16 fsm[];
    const unsigned sbase = smem_u32(fsm);

    const int tid  = threadIdx.x;
    const int bh   = blockIdx.y;         // b*16 + h
    const int qb   = blockIdx.x;         // q tile of 128
    const int wid  = tid >> 5;           // 0..7
    const int lane = tid & 31;
    const int g    = lane >> 2;
    const int t    = lane & 3;
    const int qw   = wid * 16;           // warp q-row base (local)

    const __nv_bfloat16* Qg = g_Qh + ((size_t)bh * Lv + qb * 128) * HDv;
    const __nv_bfloat16* Kg = g_Kh + (size_t)bh * Lv * HDv;
    const __nv_bfloat16* Vg = g_Vh + (size_t)bh * Lv * HDv;

    // loaders (256 threads): row = tid>>1, half = tid&1 (64B each)
    const int ld_row  = tid >> 1;        // 0..127
    const int ld_colb = (tid & 1) * 64;  // byte offset within 128B row

    // Q: 128 rows -> QP region
    {
        const __nv_bfloat16* qs = Qg + (size_t)ld_row * HDv + ld_colb / 2;
        const unsigned qd = sbase + (unsigned)(ld_row * FQS) * 2 + ld_colb;
#pragma unroll
        for (int u = 0; u < 4; u++) cp_async16(qd + u * 16, qs + u * 8);
    }
    // K/V stage loader: 128 logical rows (K 0..63, V 64..127)
    auto load_kv = [&](int kb, int stg) {
        const __nv_bfloat16* src = (ld_row < 64)
            ? Kg + (size_t)(kb * 64 + ld_row) * HDv + ld_colb / 2
            : Vg + (size_t)(kb * 64 + ld_row - 64) * HDv + ld_colb / 2;
        const unsigned dst = sbase + (unsigned)(KV_OFF + stg * STG_EL + ld_row * FQS) * 2 + ld_colb;
#pragma unroll
        for (int u = 0; u < 4; u++) cp_async16(dst + u * 16, src + u * 8);
    };

    load_kv(0, 0);
    cp_commit();
    cp_wait<0>();
    __syncthreads();

    // hoist Q fragments (M=16 per warp): qf[kc][4]
    const int a_row = lane & 15;
    const int a_k8  = (lane >> 4) << 3;
    const unsigned qA = sbase + (unsigned)((qw + a_row) * FQS + a_k8) * 2;
    unsigned qf[4][4];
#pragma unroll
    for (int kc = 0; kc < 4; kc++)
        ldsm4(qf[kc][0], qf[kc][1], qf[kc][2], qf[kc][3], qA + kc * 32);
    __syncthreads();   // all warps have Q frags; QP region now reusable for P

    // ldmatrix address components
    const int b_row = ((lane >> 4) << 3) + (lane & 7);
    const int b_k8  = ((lane >> 3) & 1) << 3;
    const int v_row = (((lane >> 3) & 1) << 3) + (lane & 7);
    const int v_col = (lane >> 4) << 3;
    const unsigned pA = qA;   // P uses the same A-fragment addressing in QP region

    float m0 = -1e30f, m1 = -1e30f, l0 = 0.f, l1 = 0.f;
    float o[8][4];
#pragma unroll
    for (int j = 0; j < 8; j++)
#pragma unroll
        for (int r = 0; r < 4; r++) o[j][r] = 0.f;

    const int NT = Lv / 64;   // 32
    for (int kb = 0; kb < NT; kb++) {
        const int stg = kb & 1;
        if (kb + 1 < NT) load_kv(kb + 1, stg ^ 1);
        cp_commit();
        cp_wait<1>();
        __syncthreads();

        const unsigned kB = sbase + (unsigned)(KV_OFF + stg * STG_EL + b_row * FQS + b_k8) * 2;
        const unsigned vB = sbase + (unsigned)(KV_OFF + stg * STG_EL + 64 * FQS + v_row * FQS + v_col) * 2;

        // ---- S = Q K^T ----
        float s[8][4];
#pragma unroll
        for (int j = 0; j < 8; j++)
#pragma unroll
            for (int r = 0; r < 4; r++) s[j][r] = 0.f;

#pragma unroll
        for (int kc = 0; kc < 4; kc++) {
#pragma unroll
            for (int jp = 0; jp < 4; jp++) {
                unsigned b0, b1, b2, b3;
                ldsm4(b0, b1, b2, b3, kB + (unsigned)(jp * 16 * FQS + kc * 16) * 2);
                mma_bf16(s[2 * jp],     qf[kc][0], qf[kc][1], qf[kc][2], qf[kc][3], b0, b1);
                mma_bf16(s[2 * jp + 1], qf[kc][0], qf[kc][1], qf[kc][2], qf[kc][3], b2, b3);
            }
        }

        // ---- online softmax (log2 domain) ----
        float rmax0 = -1e30f, rmax1 = -1e30f;
#pragma unroll
        for (int j = 0; j < 8; j++) {
            rmax0 = fmaxf(rmax0, fmaxf(s[j][0], s[j][1]));
            rmax1 = fmaxf(rmax1, fmaxf(s[j][2], s[j][3]));
        }
#pragma unroll
        for (int off = 1; off <= 2; off <<= 1) {
            rmax0 = fmaxf(rmax0, __shfl_xor_sync(0xffffffffu, rmax0, off));
            rmax1 = fmaxf(rmax1, __shfl_xor_sync(0xffffffffu, rmax1, off));
        }
        const float mn0 = fmaxf(m0, rmax0);
        const float mn1 = fmaxf(m1, rmax1);
        const float cr0 = ex2(m0 - mn0);
        const float cr1 = ex2(m1 - mn1);

        float rs0 = 0.f, rs1 = 0.f;
#pragma unroll
        for (int j = 0; j < 8; j++) {
            const float p00 = ex2(s[j][0] - mn0);
            const float p01 = ex2(s[j][1] - mn0);
            const float p10 = ex2(s[j][2] - mn1);
            const float p11 = ex2(s[j][3] - mn1);
            rs0 += p00 + p01;
            rs1 += p10 + p11;
            *(__nv_bfloat162*)&fsm[(qw + g) * FQS + j * 8 + 2 * t] =
                __float22bfloat162_rn(make_float2(p00, p01));
            *(__nv_bfloat162*)&fsm[(qw + 8 + g) * FQS + j * 8 + 2 * t] =
                __float22bfloat162_rn(make_float2(p10, p11));
        }
#pragma unroll
        for (int off = 1; off <= 2; off <<= 1) {
            rs0 += __shfl_xor_sync(0xffffffffu, rs0, off);
            rs1 += __shfl_xor_sync(0xffffffffu, rs1, off);
        }
        l0 = l0 * cr0 + rs0;
        l1 = l1 * cr1 + rs1;
        m0 = mn0; m1 = mn1;
#pragma unroll
        for (int j = 0; j < 8; j++) {
            o[j][0] *= cr0; o[j][1] *= cr0;
            o[j][2] *= cr1; o[j][3] *= cr1;
        }
        __syncwarp();

        // ---- O += P V ----
#pragma unroll
        for (int kc = 0; kc < 4; kc++) {
            unsigned pa0, pa1, pa2, pa3;
            ldsm4(pa0, pa1, pa2, pa3, pA + kc * 32);
#pragma unroll
            for (int jp = 0; jp < 4; jp++) {
                unsigned b0, b1, b2, b3;
                ldsm4t(b0, b1, b2, b3, vB + (unsigned)(kc * 16 * FQS + jp * 16) * 2);
                mma_bf16(o[2 * jp],     pa0, pa1, pa2, pa3, b0, b1);
                mma_bf16(o[2 * jp + 1], pa0, pa1, pa2, pa3, b2, b3);
            }
        }
        __syncthreads();
    }

    // ---- write O to g_O [B,L,D] (tf32-rounded for the Wo GEMM) ----
    const int b = bh >> 4, h = bh & 15;
    const float inv0 = 1.f / l0;
    const float inv1 = 1.f / l1;
    const int q0 = qb * 128 + qw + g;
    const int q1 = q0 + 8;
#pragma unroll
    for (int j = 0; j < 8; j++) {
        const int colD = h * HDv + j * 8 + 2 * t;
        float2 w0 = make_float2(__uint_as_float(f2tf32(o[j][0] * inv0)),
                                __uint_as_float(f2tf32(o[j][1] * inv0)));
        float2 w1 = make_float2(__uint_as_float(f2tf32(o[j][2] * inv1)),
                                __uint_as_float(f2tf32(o[j][3] * inv1)));
        *(float2*)&g_O[((size_t)b * Lv + q0) * Dv + colD] = w0;
        *(float2*)&g_O[((size_t)b * Lv + q1) * Dv + colD] = w1;
    }
}

// ---------------- LayerNorm: one block per row ----------------
__device__ __forceinline__ float blockReduceSum(float val)
{
    __shared__ float sh[8];
    const int lane = threadIdx.x & 31;
    const int wid  = threadIdx.x >> 5;
#pragma unroll
    for (int o = 16; o > 0; o >>= 1) val += __shfl_xor_sync(0xffffffffu, val, o);
    __syncthreads();
    if (lane == 0) sh[wid] = val;
    __syncthreads();
    if (wid == 0) {
        val = (lane < 8) ? sh[lane] : 0.f;
#pragma unroll
        for (int o = 4; o > 0; o >>= 1) val += __shfl_xor_sync(0xffffffffu, val, o);
        if (lane == 0) sh[0] = val;
    }
    __syncthreads();
    return sh[0];
}

__global__ __launch_bounds__(256)
void layernorm_kernel(const float* __restrict__ gamma,
                      const float* __restrict__ beta,
                      float* __restrict__ out)
{
    const int row = blockIdx.x;
    const int tid = threadIdx.x;
    const float* y = g_Y + (size_t)row * Dv;

    float v[4];
#pragma unroll
    for (int i = 0; i < 4; i++) v[i] = y[tid + i * 256];

    const float total = blockReduceSum(v[0] + v[1] + v[2] + v[3]);
    const float mu = total * (1.f / Dv);

    float d2 = 0.f;
#pragma unroll
    for (int i = 0; i < 4; i++) {
        const float d = v[i] - mu;
        d2 += d * d;
    }
    const float var = blockReduceSum(d2) * (1.f / Dv);
    const float rs = rsqrtf(var + EPSv);

#pragma unroll
    for (int i = 0; i < 4; i++) {
        const int c = tid + i * 256;
        out[(size_t)row * Dv + c] = (v[i] - mu) * rs * gamma[c] + beta[c];
    }
}

// ---------------- launch ----------------
extern "C" void kernel_launch(void* const* d_in, const int* in_sizes, int n_in,
                              void* d_out, int out_size)
{
    (void)in_sizes; (void)n_in; (void)out_size;
    const float* x     = (const float*)d_in[0];
    const float* Wq    = (const float*)d_in[1];
    const float* bq    = (const float*)d_in[2];
    const float* Wk    = (const float*)d_in[3];
    const float* bk    = (const float*)d_in[4];
    const float* Wv    = (const float*)d_in[5];
    const float* bv    = (const float*)d_in[6];
    const float* Wo    = (const float*)d_in[7];
    const float* bo    = (const float*)d_in[8];
    const float* gamma = (const float*)d_in[9];
    const float* beta  = (const float*)d_in[10];
    float* out = (float*)d_out;

    cudaFuncSetAttribute(flash_tc_kernel,
                         cudaFuncAttributeMaxDynamicSharedMemorySize, FLASH_SMEM);
    cudaFuncSetAttribute(gemm_tc_kernel,
                         cudaFuncAttributeMaxDynamicSharedMemorySize, GEMM_SMEM);

    float* d_xt = nullptr;
    float* d_Wt = nullptr;
    cudaGetSymbolAddress((void**)&d_xt, g_xt);
    cudaGetSymbolAddress((void**)&d_Wt, g_Wt);

    // pre-pass: tf32 rounding
    const int nx4 = Mv * Dv / 4;
    const int nw4 = Dv * Dv / 4;
    tf32_round_kernel<<<(nx4 + 255) / 256, 256>>>(x, d_xt, nx4);
    tf32_round_kernel<<<(nw4 + 255) / 256, 256>>>(Wq, d_Wt + 0 * Dv * Dv, nw4);
    tf32_round_kernel<<<(nw4 + 255) / 256, 256>>>(Wk, d_Wt + 1 * Dv * Dv, nw4);
    tf32_round_kernel<<<(nw4 + 255) / 256, 256>>>(Wv, d_Wt + 2 * Dv * Dv, nw4);
    tf32_round_kernel<<<(nw4 + 255) / 256, 256>>>(Wo, d_Wt + 3 * Dv * Dv, nw4);

    // fused QKV projection
    gemm_tc_kernel<<<dim3(24, Mv / 128), 256, GEMM_SMEM>>>(0, bq, bk, bv, nullptr, nullptr);

    // attention
    flash_tc_kernel<<<dim3(Lv / 128, Bv * Hv), 256, FLASH_SMEM>>>();

    // output projection + residual
    gemm_tc_kernel<<<dim3(8, Mv / 128), 256, GEMM_SMEM>>>(1, nullptr, nullptr, nullptr, bo, x);

    layernorm_kernel<<<Mv, 256>>>(gamma, beta, out);
}

// round 12
// speedup vs baseline: 2.1489x; 1.4262x over previous
#include <cuda_runtime.h>
#include <cuda_bf16.h>
#include <math.h>

// Problem constants
#define Bv 4
#define Lv 2048
#define Dv 1024
#define Hv 16
#define HDv 64
#define Mv (Bv * Lv)          // 8192 rows
#define EPSv 1e-5f

// ---------------- scratch (device globals; no allocs allowed) ----------------
__device__ __nv_bfloat16 g_xh[Mv * Dv];             // x in bf16
__device__ __nv_bfloat16 g_Wh[4 * Dv * Dv];         // Wq,Wk,Wv,Wo in bf16
__device__ __nv_bfloat16 g_Qh[Bv * Hv * Lv * HDv];  // [B,H,L,HD], pre-scaled
__device__ __nv_bfloat16 g_Kh[Bv * Hv * Lv * HDv];
__device__ __nv_bfloat16 g_Vh[Bv * Hv * Lv * HDv];
__device__ __nv_bfloat16 g_Oh[Mv * Dv];             // attention out, bf16 [B,L,D]
__device__ float g_Y[Mv * Dv];                      // pre-LN residual sum

// ---------------- helpers ----------------
__device__ __forceinline__ float ex2(float x) {
    float y;
    asm("ex2.approx.ftz.f32 %0, %1;" : "=f"(y) : "f"(x));
    return y;
}

__device__ __forceinline__ unsigned smem_u32(const void* p) {
    return (unsigned)__cvta_generic_to_shared(p);
}

__device__ __forceinline__ void cp_async16(unsigned dst, const void* src) {
    asm volatile("cp.async.cg.shared.global [%0], [%1], 16;" :: "r"(dst), "l"(src));
}
__device__ __forceinline__ void cp_commit() {
    asm volatile("cp.async.commit_group;");
}
template<int N> __device__ __forceinline__ void cp_wait() {
    asm volatile("cp.async.wait_group %0;" :: "n"(N));
}

__device__ __forceinline__ void mma_bf16(float* c, unsigned a0, unsigned a1, unsigned a2, unsigned a3,
                                         unsigned b0, unsigned b1) {
    asm volatile(
        "mma.sync.aligned.m16n8k16.row.col.f32.bf16.bf16.f32 "
        "{%0,%1,%2,%3}, {%4,%5,%6,%7}, {%8,%9}, {%0,%1,%2,%3};"
        : "+f"(c[0]), "+f"(c[1]), "+f"(c[2]), "+f"(c[3])
        : "r"(a0), "r"(a1), "r"(a2), "r"(a3), "r"(b0), "r"(b1));
}

__device__ __forceinline__ void ldsm4(unsigned& r0, unsigned& r1, unsigned& r2, unsigned& r3, unsigned addr) {
    asm volatile("ldmatrix.sync.aligned.m8n8.x4.shared.b16 {%0,%1,%2,%3}, [%4];"
                 : "=r"(r0), "=r"(r1), "=r"(r2), "=r"(r3) : "r"(addr));
}
__device__ __forceinline__ void ldsm4t(unsigned& r0, unsigned& r1, unsigned& r2, unsigned& r3, unsigned addr) {
    asm volatile("ldmatrix.sync.aligned.m8n8.x4.trans.shared.b16 {%0,%1,%2,%3}, [%4];"
                 : "=r"(r0), "=r"(r1), "=r"(r2), "=r"(r3) : "r"(addr));
}

// ---------------- pre-pass: fp32 -> bf16 ----------------
__global__ __launch_bounds__(256)
void bf16_cvt_kernel(const float* __restrict__ src, __nv_bfloat16* __restrict__ dst, int n4)
{
    const int i = blockIdx.x * 256 + threadIdx.x;
    if (i < n4) {
        float4 v = ((const float4*)src)[i];
        __nv_bfloat162 lo = __float22bfloat162_rn(make_float2(v.x, v.y));
        __nv_bfloat162 hi = __float22bfloat162_rn(make_float2(v.z, v.w));
        uint2 pack;
        pack.x = *(unsigned*)&lo;
        pack.y = *(unsigned*)&hi;
        ((uint2*)dst)[i] = pack;
    }
}

// ---------------- bf16 tensor-core GEMM, 3-stage cp.async pipeline ----------------
// mode 0: fused QKV. grid (24, 64). A = g_xh, W = g_Wh[wsel], out bf16 head-split.
// mode 1: Wo.        grid (8, 64).  A = g_Oh, W = g_Wh[3],  out g_Y fp32 (+residual x).
// BM=128, BN=128, BK=32. 256 threads = 8 warps (2 x 4), warp tile 64x32.
#define GSTAGES 3
#define ASTR 40                         // 32 + 8 pad (bf16) -> 80B rows
#define BSTR 136                        // 128 + 8 pad (bf16) -> 272B rows
#define A_STAGE (128 * ASTR)            // 5120 el
#define B_STAGE (32 * BSTR)             // 4352 el
#define GEMM_SMEM (GSTAGES * (A_STAGE + B_STAGE) * 2)   // 56832 B

__global__ __launch_bounds__(256, 2)
void gemm_tc_kernel(int mode,
                    const float* __restrict__ bq, const float* __restrict__ bk,
                    const float* __restrict__ bv, const float* __restrict__ bo,
                    const float* __restrict__ xres)
{
    extern __shared__ __nv_bfloat16 gsm[];
    __nv_bfloat16* sA = gsm;
    __nv_bfloat16* sB = gsm + GSTAGES * A_STAGE;

    const __nv_bfloat16* A;
    const __nv_bfloat16* W;
    const float* bias;
    int wsel, bcol;
    if (mode == 0) {
        wsel = blockIdx.x >> 3;
        bcol = blockIdx.x & 7;
        A = g_xh;
        W = g_Wh + (size_t)wsel * Dv * Dv;
        bias = (wsel == 0) ? bq : ((wsel == 1) ? bk : bv);
    } else {
        wsel = 3;
        bcol = blockIdx.x;
        A = g_Oh;
        W = g_Wh + (size_t)3 * Dv * Dv;
        bias = bo;
    }

    const int tid  = threadIdx.x;
    const int brow = blockIdx.y;
    const int wid  = tid >> 5;
    const int lane = tid & 31;
    const int wm   = wid & 1;
    const int wn   = wid >> 1;
    const int row4 = lane >> 2;
    const int col  = lane & 3;

    // copy mapping: A 512 16B-chunks (row = c>>2, kc = (c&3)*8), B 512 (row = c>>4, nc = (c&15)*8)
    const int ac0_row = tid >> 2,          ac_kc = (tid & 3) * 8;
    const int ac1_row = (tid + 256) >> 2;
    const int bc0_row = tid >> 4,          bc_nc = (tid & 15) * 8;
    const int bc1_row = (tid + 256) >> 4;

    const __nv_bfloat16* Agb = A + (size_t)(brow * 128) * Dv;
    const __nv_bfloat16* Wgb = W + bcol * 128;

    float acc[4][4][4];
#pragma unroll
    for (int i = 0; i < 4; i++)
#pragma unroll
        for (int j = 0; j < 4; j++)
#pragma unroll
            for (int r = 0; r < 4; r++) acc[i][j][r] = 0.f;

    auto copy_stage = [&](int s, int k0) {
        __nv_bfloat16* as = sA + s * A_STAGE;
        __nv_bfloat16* bs = sB + s * B_STAGE;
        cp_async16(smem_u32(as + ac0_row * ASTR + ac_kc),
                   Agb + (size_t)ac0_row * Dv + k0 + ac_kc);
        cp_async16(smem_u32(as + ac1_row * ASTR + ac_kc),
                   Agb + (size_t)ac1_row * Dv + k0 + ac_kc);
        cp_async16(smem_u32(bs + bc0_row * BSTR + bc_nc),
                   Wgb + (size_t)(k0 + bc0_row) * Dv + bc_nc);
        cp_async16(smem_u32(bs + bc1_row * BSTR + bc_nc),
                   Wgb + (size_t)(k0 + bc1_row) * Dv + bc_nc);
    };

    const int NK = Dv / 32;   // 32
#pragma unroll
    for (int s = 0; s < GSTAGES - 1; s++) {
        copy_stage(s, s * 32);
        cp_commit();
    }

    int stg_c = 0;                 // compute stage
    int stg_l = GSTAGES - 1;       // load stage
    for (int kt = 0; kt < NK; kt++) {
        cp_wait<GSTAGES - 2>();
        __syncthreads();

        const int nxt = kt + GSTAGES - 1;
        if (nxt < NK) copy_stage(stg_l, nxt * 32);
        cp_commit();

        const __nv_bfloat16* as = sA + stg_c * A_STAGE;
        const __nv_bfloat16* bs = sB + stg_c * B_STAGE;

        // ldmatrix bases
        const unsigned aB = smem_u32(as) +
            (unsigned)((wm * 64 + (lane & 15)) * ASTR + ((lane >> 4) << 3)) * 2;
        const unsigned bB = smem_u32(bs) +
            (unsigned)(((((lane >> 3) & 1) << 3) + (lane & 7)) * BSTR +
                       wn * 32 + ((lane >> 4) << 3)) * 2;

#pragma unroll
        for (int kc = 0; kc < 2; kc++) {
            unsigned af[4][4];
#pragma unroll
            for (int i = 0; i < 4; i++)
                ldsm4(af[i][0], af[i][1], af[i][2], af[i][3],
                      aB + (unsigned)(i * 16 * ASTR + kc * 16) * 2);
#pragma unroll
            for (int jp = 0; jp < 2; jp++) {
                unsigned b0, b1, b2, b3;
                ldsm4t(b0, b1, b2, b3, bB + (unsigned)(kc * 16 * BSTR + jp * 16) * 2);
#pragma unroll
                for (int i = 0; i < 4; i++) {
                    mma_bf16(acc[i][2 * jp],     af[i][0], af[i][1], af[i][2], af[i][3], b0, b1);
                    mma_bf16(acc[i][2 * jp + 1], af[i][0], af[i][1], af[i][2], af[i][3], b2, b3);
                }
            }
        }
        __syncthreads();
        stg_c = (stg_c == GSTAGES - 1) ? 0 : stg_c + 1;
        stg_l = (stg_l == GSTAGES - 1) ? 0 : stg_l + 1;
    }

    // epilogue
    const float qsc = 0.125f * 1.4426950408889634f;  // 1/sqrt(64) * log2(e)
#pragma unroll
    for (int i = 0; i < 4; i++) {
#pragma unroll
        for (int j = 0; j < 4; j++) {
            const int m_lo = brow * 128 + wm * 64 + i * 16 + row4;
            const int n0   = bcol * 128 + wn * 32 + j * 8 + col * 2;
#pragma unroll
            for (int half = 0; half < 2; half++) {
                const int m = m_lo + half * 8;
                float v0 = acc[i][j][half * 2 + 0] + bias[n0];
                float v1 = acc[i][j][half * 2 + 1] + bias[n0 + 1];
                if (mode == 1) {
                    v0 += xres[(size_t)m * Dv + n0];
                    v1 += xres[(size_t)m * Dv + n0 + 1];
                    *(float2*)&g_Y[(size_t)m * Dv + n0] = make_float2(v0, v1);
                } else {
                    if (wsel == 0) { v0 *= qsc; v1 *= qsc; }
                    const int b = m >> 11, l = m & 2047;
                    const int h = n0 >> 6, hd = n0 & 63;
                    const size_t idx = ((((size_t)b * Hv + h) * Lv) + l) * HDv + hd;
                    __nv_bfloat16* dst = (wsel == 0) ? g_Qh : ((wsel == 1) ? g_Kh : g_Vh);
                    *(__nv_bfloat162*)&dst[idx] = __float22bfloat162_rn(make_float2(v0, v1));
                }
            }
        }
    }
}

// ---------------- bf16 flash attention: 256 thr / 8 warps, warp M=16 ----------------
// Br=128, Bc=64. Q hoisted into registers (smem region reused for P).
// K/V double-buffered via cp.async. smem bf16, row stride 72 (144B rows).
#define FQS 72
#define KV_OFF (128 * FQS)
#define STG_EL (128 * FQS)
#define FLASH_SMEM ((KV_OFF + 2 * STG_EL) * 2)   // 55296 B

__global__ __launch_bounds__(256, 2)
void flash_tc_kernel()
{
    extern __shared__ __nv_bfloat16 fsm[];
    const unsigned sbase = smem_u32(fsm);

    const int tid  = threadIdx.x;
    const int bh   = blockIdx.y;         // b*16 + h
    const int qb   = blockIdx.x;         // q tile of 128
    const int wid  = tid >> 5;           // 0..7
    const int lane = tid & 31;
    const int g    = lane >> 2;
    const int t    = lane & 3;
    const int qw   = wid * 16;

    const __nv_bfloat16* Qg = g_Qh + ((size_t)bh * Lv + qb * 128) * HDv;
    const __nv_bfloat16* Kg = g_Kh + (size_t)bh * Lv * HDv;
    const __nv_bfloat16* Vg = g_Vh + (size_t)bh * Lv * HDv;

    const int ld_row  = tid >> 1;
    const int ld_colb = (tid & 1) * 64;

    // Q: 128 rows -> QP region
    {
        const __nv_bfloat16* qs = Qg + (size_t)ld_row * HDv + ld_colb / 2;
        const unsigned qd = sbase + (unsigned)(ld_row * FQS) * 2 + ld_colb;
#pragma unroll
        for (int u = 0; u < 4; u++) cp_async16(qd + u * 16, qs + u * 8);
    }
    auto load_kv = [&](int kb, int stg) {
        const __nv_bfloat16* src = (ld_row < 64)
            ? Kg + (size_t)(kb * 64 + ld_row) * HDv + ld_colb / 2
            : Vg + (size_t)(kb * 64 + ld_row - 64) * HDv + ld_colb / 2;
        const unsigned dst = sbase + (unsigned)(KV_OFF + stg * STG_EL + ld_row * FQS) * 2 + ld_colb;
#pragma unroll
        for (int u = 0; u < 4; u++) cp_async16(dst + u * 16, src + u * 8);
    };

    load_kv(0, 0);
    cp_commit();
    cp_wait<0>();
    __syncthreads();

    // hoist Q fragments
    const int a_row = lane & 15;
    const int a_k8  = (lane >> 4) << 3;
    const unsigned qA = sbase + (unsigned)((qw + a_row) * FQS + a_k8) * 2;
    unsigned qf[4][4];
#pragma unroll
    for (int kc = 0; kc < 4; kc++)
        ldsm4(qf[kc][0], qf[kc][1], qf[kc][2], qf[kc][3], qA + kc * 32);
    __syncthreads();

    const int b_row = ((lane >> 4) << 3) + (lane & 7);
    const int b_k8  = ((lane >> 3) & 1) << 3;
    const int v_row = (((lane >> 3) & 1) << 3) + (lane & 7);
    const int v_col = (lane >> 4) << 3;
    const unsigned pA = qA;

    float m0 = -1e30f, m1 = -1e30f, l0 = 0.f, l1 = 0.f;
    float o[8][4];
#pragma unroll
    for (int j = 0; j < 8; j++)
#pragma unroll
        for (int r = 0; r < 4; r++) o[j][r] = 0.f;

    const int NT = Lv / 64;
    for (int kb = 0; kb < NT; kb++) {
        const int stg = kb & 1;
        if (kb + 1 < NT) load_kv(kb + 1, stg ^ 1);
        cp_commit();
        cp_wait<1>();
        __syncthreads();

        const unsigned kB = sbase + (unsigned)(KV_OFF + stg * STG_EL + b_row * FQS + b_k8) * 2;
        const unsigned vB = sbase + (unsigned)(KV_OFF + stg * STG_EL + 64 * FQS + v_row * FQS + v_col) * 2;

        // ---- S = Q K^T ----
        float s[8][4];
#pragma unroll
        for (int j = 0; j < 8; j++)
#pragma unroll
            for (int r = 0; r < 4; r++) s[j][r] = 0.f;

#pragma unroll
        for (int kc = 0; kc < 4; kc++) {
#pragma unroll
            for (int jp = 0; jp < 4; jp++) {
                unsigned b0, b1, b2, b3;
                ldsm4(b0, b1, b2, b3, kB + (unsigned)(jp * 16 * FQS + kc * 16) * 2);
                mma_bf16(s[2 * jp],     qf[kc][0], qf[kc][1], qf[kc][2], qf[kc][3], b0, b1);
                mma_bf16(s[2 * jp + 1], qf[kc][0], qf[kc][1], qf[kc][2], qf[kc][3], b2, b3);
            }
        }

        // ---- online softmax (log2 domain) ----
        float rmax0 = -1e30f, rmax1 = -1e30f;
#pragma unroll
        for (int j = 0; j < 8; j++) {
            rmax0 = fmaxf(rmax0, fmaxf(s[j][0], s[j][1]));
            rmax1 = fmaxf(rmax1, fmaxf(s[j][2], s[j][3]));
        }
#pragma unroll
        for (int off = 1; off <= 2; off <<= 1) {
            rmax0 = fmaxf(rmax0, __shfl_xor_sync(0xffffffffu, rmax0, off));
            rmax1 = fmaxf(rmax1, __shfl_xor_sync(0xffffffffu, rmax1, off));
        }
        const float mn0 = fmaxf(m0, rmax0);
        const float mn1 = fmaxf(m1, rmax1);
        const float cr0 = ex2(m0 - mn0);
        const float cr1 = ex2(m1 - mn1);

        float rs0 = 0.f, rs1 = 0.f;
#pragma unroll
        for (int j = 0; j < 8; j++) {
            const float p00 = ex2(s[j][0] - mn0);
            const float p01 = ex2(s[j][1] - mn0);
            const float p10 = ex2(s[j][2] - mn1);
            const float p11 = ex2(s[j][3] - mn1);
            rs0 += p00 + p01;
            rs1 += p10 + p11;
            *(__nv_bfloat162*)&fsm[(qw + g) * FQS + j * 8 + 2 * t] =
                __float22bfloat162_rn(make_float2(p00, p01));
            *(__nv_bfloat162*)&fsm[(qw + 8 + g) * FQS + j * 8 + 2 * t] =
                __float22bfloat162_rn(make_float2(p10, p11));
        }
#pragma unroll
        for (int off = 1; off <= 2; off <<= 1) {
            rs0 += __shfl_xor_sync(0xffffffffu, rs0, off);
            rs1 += __shfl_xor_sync(0xffffffffu, rs1, off);
        }
        l0 = l0 * cr0 + rs0;
        l1 = l1 * cr1 + rs1;
        m0 = mn0; m1 = mn1;
#pragma unroll
        for (int j = 0; j < 8; j++) {
            o[j][0] *= cr0; o[j][1] *= cr0;
            o[j][2] *= cr1; o[j][3] *= cr1;
        }
        __syncwarp();

        // ---- O += P V ----
#pragma unroll
        for (int kc = 0; kc < 4; kc++) {
            unsigned pa0, pa1, pa2, pa3;
            ldsm4(pa0, pa1, pa2, pa3, pA + kc * 32);
#pragma unroll
            for (int jp = 0; jp < 4; jp++) {
                unsigned b0, b1, b2, b3;
                ldsm4t(b0, b1, b2, b3, vB + (unsigned)(kc * 16 * FQS + jp * 16) * 2);
                mma_bf16(o[2 * jp],     pa0, pa1, pa2, pa3, b0, b1);
                mma_bf16(o[2 * jp + 1], pa0, pa1, pa2, pa3, b2, b3);
            }
        }
        __syncthreads();
    }

    // ---- write O to g_Oh [B,L,D] in bf16 ----
    const int b = bh >> 4, h = bh & 15;
    const float inv0 = 1.f / l0;
    const float inv1 = 1.f / l1;
    const int q0 = qb * 128 + qw + g;
    const int q1 = q0 + 8;
#pragma unroll
    for (int j = 0; j < 8; j++) {
        const int colD = h * HDv + j * 8 + 2 * t;
        *(__nv_bfloat162*)&g_Oh[((size_t)b * Lv + q0) * Dv + colD] =
            __float22bfloat162_rn(make_float2(o[j][0] * inv0, o[j][1] * inv0));
        *(__nv_bfloat162*)&g_Oh[((size_t)b * Lv + q1) * Dv + colD] =
            __float22bfloat162_rn(make_float2(o[j][2] * inv1, o[j][3] * inv1));
    }
}

// ---------------- LayerNorm: one block per row ----------------
__device__ __forceinline__ float blockReduceSum(float val)
{
    __shared__ float sh[8];
    const int lane = threadIdx.x & 31;
    const int wid  = threadIdx.x >> 5;
#pragma unroll
    for (int o = 16; o > 0; o >>= 1) val += __shfl_xor_sync(0xffffffffu, val, o);
    __syncthreads();
    if (lane == 0) sh[wid] = val;
    __syncthreads();
    if (wid == 0) {
        val = (lane < 8) ? sh[lane] : 0.f;
#pragma unroll
        for (int o = 4; o > 0; o >>= 1) val += __shfl_xor_sync(0xffffffffu, val, o);
        if (lane == 0) sh[0] = val;
    }
    __syncthreads();
    return sh[0];
}

__global__ __launch_bounds__(256)
void layernorm_kernel(const float* __restrict__ gamma,
                      const float* __restrict__ beta,
                      float* __restrict__ out)
{
    const int row = blockIdx.x;
    const int tid = threadIdx.x;
    const float* y = g_Y + (size_t)row * Dv;

    float v[4];
#pragma unroll
    for (int i = 0; i < 4; i++) v[i] = y[tid + i * 256];

    const float total = blockReduceSum(v[0] + v[1] + v[2] + v[3]);
    const float mu = total * (1.f / Dv);

    float d2 = 0.f;
#pragma unroll
    for (int i = 0; i < 4; i++) {
        const float d = v[i] - mu;
        d2 += d * d;
    }
    const float var = blockReduceSum(d2) * (1.f / Dv);
    const float rs = rsqrtf(var + EPSv);

#pragma unroll
    for (int i = 0; i < 4; i++) {
        const int c = tid + i * 256;
        out[(size_t)row * Dv + c] = (v[i] - mu) * rs * gamma[c] + beta[c];
    }
}

// ---------------- launch ----------------
extern "C" void kernel_launch(void* const* d_in, const int* in_sizes, int n_in,
                              void* d_out, int out_size)
{
    (void)in_sizes; (void)n_in; (void)out_size;
    const float* x     = (const float*)d_in[0];
    const float* Wq    = (const float*)d_in[1];
    const float* bq    = (const float*)d_in[2];
    const float* Wk    = (const float*)d_in[3];
    const float* bk    = (const float*)d_in[4];
    const float* Wv    = (const float*)d_in[5];
    const float* bv    = (const float*)d_in[6];
    const float* Wo    = (const float*)d_in[7];
    const float* bo    = (const float*)d_in[8];
    const float* gamma = (const float*)d_in[9];
    const float* beta  = (const float*)d_in[10];
    float* out = (float*)d_out;

    cudaFuncSetAttribute(flash_tc_kernel,
                         cudaFuncAttributeMaxDynamicSharedMemorySize, FLASH_SMEM);
    cudaFuncSetAttribute(gemm_tc_kernel,
                         cudaFuncAttributeMaxDynamicSharedMemorySize, GEMM_SMEM);

    __nv_bfloat16* d_xh = nullptr;
    __nv_bfloat16* d_Wh = nullptr;
    cudaGetSymbolAddress((void**)&d_xh, g_xh);
    cudaGetSymbolAddress((void**)&d_Wh, g_Wh);

    // pre-pass: fp32 -> bf16
    const int nx4 = Mv * Dv / 4;
    const int nw4 = Dv * Dv / 4;
    bf16_cvt_kernel<<<(nx4 + 255) / 256, 256>>>(x, d_xh, nx4);
    bf16_cvt_kernel<<<(nw4 + 255) / 256, 256>>>(Wq, d_Wh + (size_t)0 * Dv * Dv, nw4);
    bf16_cvt_kernel<<<(nw4 + 255) / 256, 256>>>(Wk, d_Wh + (size_t)1 * Dv * Dv, nw4);
    bf16_cvt_kernel<<<(nw4 + 255) / 256, 256>>>(Wv, d_Wh + (size_t)2 * Dv * Dv, nw4);
    bf16_cvt_kernel<<<(nw4 + 255) / 256, 256>>>(Wo, d_Wh + (size_t)3 * Dv * Dv, nw4);

    // fused QKV projection
    gemm_tc_kernel<<<dim3(24, Mv / 128), 256, GEMM_SMEM>>>(0, bq, bk, bv, nullptr, nullptr);

    // attention
    flash_tc_kernel<<<dim3(Lv / 128, Bv * Hv), 256, FLASH_SMEM>>>();

    // output projection + residual
    gemm_tc_kernel<<<dim3(8, Mv / 128), 256, GEMM_SMEM>>>(1, nullptr, nullptr, nullptr, bo, x);

    layernorm_kernel<<<Mv, 256>>>(gamma, beta, out);
}

// round 13
// speedup vs baseline: 2.2363x; 1.0407x over previous
#include <cuda_runtime.h>
#include <cuda_bf16.h>
#include <cuda_fp16.h>
#include <math.h>

// Problem constants
#define Bv 4
#define Lv 2048
#define Dv 1024
#define Hv 16
#define HDv 64
#define Mv (Bv * Lv)          // 8192 rows
#define EPSv 1e-5f

// ---------------- scratch (device globals; no allocs allowed) ----------------
__device__ __nv_bfloat16 g_xh[Mv * Dv];             // x in bf16
__device__ __nv_bfloat16 g_Wh[4 * Dv * Dv];         // Wq,Wk,Wv,Wo in bf16
__device__ __nv_bfloat16 g_Qh[Bv * Hv * Lv * HDv];  // [B,H,L,HD], pre-scaled
__device__ __nv_bfloat16 g_Kh[Bv * Hv * Lv * HDv];
__device__ __half        g_Vh[Bv * Hv * Lv * HDv];  // V in fp16 (PV mma is f16)
__device__ __nv_bfloat16 g_Oh[Mv * Dv];             // attention out, bf16 [B,L,D]
__device__ float g_Y[Mv * Dv];                      // pre-LN residual sum

// ---------------- helpers ----------------
__device__ __forceinline__ float ex2(float x) {
    float y;
    asm("ex2.approx.ftz.f32 %0, %1;" : "=f"(y) : "f"(x));
    return y;
}

__device__ __forceinline__ unsigned smem_u32(const void* p) {
    return (unsigned)__cvta_generic_to_shared(p);
}

__device__ __forceinline__ void cp_async16(unsigned dst, const void* src) {
    asm volatile("cp.async.cg.shared.global [%0], [%1], 16;" :: "r"(dst), "l"(src));
}
__device__ __forceinline__ void cp_commit() {
    asm volatile("cp.async.commit_group;");
}
template<int N> __device__ __forceinline__ void cp_wait() {
    asm volatile("cp.async.wait_group %0;" :: "n"(N));
}

__device__ __forceinline__ void mma_bf16(float* c, unsigned a0, unsigned a1, unsigned a2, unsigned a3,
                                         unsigned b0, unsigned b1) {
    asm volatile(
        "mma.sync.aligned.m16n8k16.row.col.f32.bf16.bf16.f32 "
        "{%0,%1,%2,%3}, {%4,%5,%6,%7}, {%8,%9}, {%0,%1,%2,%3};"
        : "+f"(c[0]), "+f"(c[1]), "+f"(c[2]), "+f"(c[3])
        : "r"(a0), "r"(a1), "r"(a2), "r"(a3), "r"(b0), "r"(b1));
}

__device__ __forceinline__ void mma_f16(float* c, unsigned a0, unsigned a1, unsigned a2, unsigned a3,
                                        unsigned b0, unsigned b1) {
    asm volatile(
        "mma.sync.aligned.m16n8k16.row.col.f32.f16.f16.f32 "
        "{%0,%1,%2,%3}, {%4,%5,%6,%7}, {%8,%9}, {%0,%1,%2,%3};"
        : "+f"(c[0]), "+f"(c[1]), "+f"(c[2]), "+f"(c[3])
        : "r"(a0), "r"(a1), "r"(a2), "r"(a3), "r"(b0), "r"(b1));
}

__device__ __forceinline__ void ldsm4(unsigned& r0, unsigned& r1, unsigned& r2, unsigned& r3, unsigned addr) {
    asm volatile("ldmatrix.sync.aligned.m8n8.x4.shared.b16 {%0,%1,%2,%3}, [%4];"
                 : "=r"(r0), "=r"(r1), "=r"(r2), "=r"(r3) : "r"(addr));
}
__device__ __forceinline__ void ldsm4t(unsigned& r0, unsigned& r1, unsigned& r2, unsigned& r3, unsigned addr) {
    asm volatile("ldmatrix.sync.aligned.m8n8.x4.trans.shared.b16 {%0,%1,%2,%3}, [%4];"
                 : "=r"(r0), "=r"(r1), "=r"(r2), "=r"(r3) : "r"(addr));
}

// pack exp2(a - m), exp2(b - m) into one f16x2 via HMUFU
__device__ __forceinline__ unsigned exp2_f16x2(float a, float b, float m) {
    unsigned r;
    asm("cvt.rn.f16x2.f32 %0, %1, %2;" : "=r"(r) : "f"(b - m), "f"(a - m)); // hi=b-m, lo=a-m
    asm("ex2.approx.f16x2 %0, %0;" : "+r"(r));
    return r;
}

// ---------------- pre-pass: fp32 -> bf16 ----------------
__global__ __launch_bounds__(256)
void bf16_cvt_kernel(const float* __restrict__ s0, const float* __restrict__ s1,
                     const float* __restrict__ s2, const float* __restrict__ s3,
                     __nv_bfloat16* __restrict__ dst, int n4)
{
    const int i = blockIdx.x * 256 + threadIdx.x;
    const float* src = (blockIdx.y == 0) ? s0 : ((blockIdx.y == 1) ? s1 : ((blockIdx.y == 2) ? s2 : s3));
    if (i < n4 && src) {
        float4 v = ((const float4*)src)[i];
        __nv_bfloat162 lo = __float22bfloat162_rn(make_float2(v.x, v.y));
        __nv_bfloat162 hi = __float22bfloat162_rn(make_float2(v.z, v.w));
        uint2 pack;
        pack.x = *(unsigned*)&lo;
        pack.y = *(unsigned*)&hi;
        ((uint2*)(dst + (size_t)blockIdx.y * Dv * Dv))[i] = pack;
    }
}

__global__ __launch_bounds__(256)
void bf16_cvt_x_kernel(const float* __restrict__ src, __nv_bfloat16* __restrict__ dst, int n4)
{
    const int i = blockIdx.x * 256 + threadIdx.x;
    if (i < n4) {
        float4 v = ((const float4*)src)[i];
        __nv_bfloat162 lo = __float22bfloat162_rn(make_float2(v.x, v.y));
        __nv_bfloat162 hi = __float22bfloat162_rn(make_float2(v.z, v.w));
        uint2 pack;
        pack.x = *(unsigned*)&lo;
        pack.y = *(unsigned*)&hi;
        ((uint2*)dst)[i] = pack;
    }
}

// ---------------- bf16 tensor-core GEMM, 3-stage cp.async pipeline ----------------
// mode 0: fused QKV. grid (24, 64). A = g_xh, W = g_Wh[wsel], out Q/K bf16, V fp16.
// mode 1: Wo.        grid (8, 64).  A = g_Oh, W = g_Wh[3], out g_Y fp32 (+residual x).
#define GSTAGES 3
#define ASTR 40
#define BSTR 136
#define A_STAGE (128 * ASTR)
#define B_STAGE (32 * BSTR)
#define GEMM_SMEM (GSTAGES * (A_STAGE + B_STAGE) * 2)   // 56832 B

__global__ __launch_bounds__(256, 2)
void gemm_tc_kernel(int mode,
                    const float* __restrict__ bq, const float* __restrict__ bk,
                    const float* __restrict__ bv, const float* __restrict__ bo,
                    const float* __restrict__ xres)
{
    extern __shared__ __nv_bfloat16 gsm[];
    __nv_bfloat16* sA = gsm;
    __nv_bfloat16* sB = gsm + GSTAGES * A_STAGE;

    const __nv_bfloat16* A;
    const __nv_bfloat16* W;
    const float* bias;
    int wsel, bcol;
    if (mode == 0) {
        wsel = blockIdx.x >> 3;
        bcol = blockIdx.x & 7;
        A = g_xh;
        W = g_Wh + (size_t)wsel * Dv * Dv;
        bias = (wsel == 0) ? bq : ((wsel == 1) ? bk : bv);
    } else {
        wsel = 3;
        bcol = blockIdx.x;
        A = g_Oh;
        W = g_Wh + (size_t)3 * Dv * Dv;
        bias = bo;
    }

    const int tid  = threadIdx.x;
    const int brow = blockIdx.y;
    const int wid  = tid >> 5;
    const int lane = tid & 31;
    const int wm   = wid & 1;
    const int wn   = wid >> 1;
    const int row4 = lane >> 2;
    const int col  = lane & 3;

    const int ac0_row = tid >> 2,          ac_kc = (tid & 3) * 8;
    const int ac1_row = (tid + 256) >> 2;
    const int bc0_row = tid >> 4,          bc_nc = (tid & 15) * 8;
    const int bc1_row = (tid + 256) >> 4;

    const __nv_bfloat16* Agb = A + (size_t)(brow * 128) * Dv;
    const __nv_bfloat16* Wgb = W + bcol * 128;

    float acc[4][4][4];
#pragma unroll
    for (int i = 0; i < 4; i++)
#pragma unroll
        for (int j = 0; j < 4; j++)
#pragma unroll
            for (int r = 0; r < 4; r++) acc[i][j][r] = 0.f;

    auto copy_stage = [&](int s, int k0) {
        __nv_bfloat16* as = sA + s * A_STAGE;
        __nv_bfloat16* bs = sB + s * B_STAGE;
        cp_async16(smem_u32(as + ac0_row * ASTR + ac_kc),
                   Agb + (size_t)ac0_row * Dv + k0 + ac_kc);
        cp_async16(smem_u32(as + ac1_row * ASTR + ac_kc),
                   Agb + (size_t)ac1_row * Dv + k0 + ac_kc);
        cp_async16(smem_u32(bs + bc0_row * BSTR + bc_nc),
                   Wgb + (size_t)(k0 + bc0_row) * Dv + bc_nc);
        cp_async16(smem_u32(bs + bc1_row * BSTR + bc_nc),
                   Wgb + (size_t)(k0 + bc1_row) * Dv + bc_nc);
    };

    const int NK = Dv / 32;
#pragma unroll
    for (int s = 0; s < GSTAGES - 1; s++) {
        copy_stage(s, s * 32);
        cp_commit();
    }

    int stg_c = 0;
    int stg_l = GSTAGES - 1;
    for (int kt = 0; kt < NK; kt++) {
        cp_wait<GSTAGES - 2>();
        __syncthreads();

        const int nxt = kt + GSTAGES - 1;
        if (nxt < NK) copy_stage(stg_l, nxt * 32);
        cp_commit();

        const __nv_bfloat16* as = sA + stg_c * A_STAGE;
        const __nv_bfloat16* bs = sB + stg_c * B_STAGE;

        const unsigned aB = smem_u32(as) +
            (unsigned)((wm * 64 + (lane & 15)) * ASTR + ((lane >> 4) << 3)) * 2;
        const unsigned bB = smem_u32(bs) +
            (unsigned)(((((lane >> 3) & 1) << 3) + (lane & 7)) * BSTR +
                       wn * 32 + ((lane >> 4) << 3)) * 2;

#pragma unroll
        for (int kc = 0; kc < 2; kc++) {
            unsigned af[4][4];
#pragma unroll
            for (int i = 0; i < 4; i++)
                ldsm4(af[i][0], af[i][1], af[i][2], af[i][3],
                      aB + (unsigned)(i * 16 * ASTR + kc * 16) * 2);
#pragma unroll
            for (int jp = 0; jp < 2; jp++) {
                unsigned b0, b1, b2, b3;
                ldsm4t(b0, b1, b2, b3, bB + (unsigned)(kc * 16 * BSTR + jp * 16) * 2);
#pragma unroll
                for (int i = 0; i < 4; i++) {
                    mma_bf16(acc[i][2 * jp],     af[i][0], af[i][1], af[i][2], af[i][3], b0, b1);
                    mma_bf16(acc[i][2 * jp + 1], af[i][0], af[i][1], af[i][2], af[i][3], b2, b3);
                }
            }
        }
        __syncthreads();
        stg_c = (stg_c == GSTAGES - 1) ? 0 : stg_c + 1;
        stg_l = (stg_l == GSTAGES - 1) ? 0 : stg_l + 1;
    }

    // epilogue
    const float qsc = 0.125f * 1.4426950408889634f;
#pragma unroll
    for (int i = 0; i < 4; i++) {
#pragma unroll
        for (int j = 0; j < 4; j++) {
            const int m_lo = brow * 128 + wm * 64 + i * 16 + row4;
            const int n0   = bcol * 128 + wn * 32 + j * 8 + col * 2;
#pragma unroll
            for (int half = 0; half < 2; half++) {
                const int m = m_lo + half * 8;
                float v0 = acc[i][j][half * 2 + 0] + bias[n0];
                float v1 = acc[i][j][half * 2 + 1] + bias[n0 + 1];
                if (mode == 1) {
                    v0 += xres[(size_t)m * Dv + n0];
                    v1 += xres[(size_t)m * Dv + n0 + 1];
                    *(float2*)&g_Y[(size_t)m * Dv + n0] = make_float2(v0, v1);
                } else {
                    const int b = m >> 11, l = m & 2047;
                    const int h = n0 >> 6, hd = n0 & 63;
                    const size_t idx = ((((size_t)b * Hv + h) * Lv) + l) * HDv + hd;
                    if (wsel == 2) {
                        *(__half2*)&g_Vh[idx] = __float22half2_rn(make_float2(v0, v1));
                    } else {
                        if (wsel == 0) { v0 *= qsc; v1 *= qsc; }
                        __nv_bfloat16* dst = (wsel == 0) ? g_Qh : g_Kh;
                        *(__nv_bfloat162*)&dst[idx] = __float22bfloat162_rn(make_float2(v0, v1));
                    }
                }
            }
        }
    }
}

// ---------------- flash attention: bf16 QK^T, f16 exp + f16 PV ----------------
// 256 thr / 8 warps, Br=128, Bc=64, warp M=16. Q hoisted (region reused for P).
// K/V double-buffered via cp.async. smem rows stride 72 el (144B).
#define FQS 72
#define KV_OFF (128 * FQS)
#define STG_EL (128 * FQS)
#define FLASH_SMEM ((KV_OFF + 2 * STG_EL) * 2)   // 55296 B
#define ONES_F16X2 0x3C003C00u

__global__ __launch_bounds__(256, 2)
void flash_tc_kernel()
{
    extern __shared__ __nv_bfloat16 fsm[];
    const unsigned sbase = smem_u32(fsm);

    const int tid  = threadIdx.x;
    const int bh   = blockIdx.y;
    const int qb   = blockIdx.x;
    const int wid  = tid >> 5;
    const int lane = tid & 31;
    const int g    = lane >> 2;
    const int t    = lane & 3;
    const int qw   = wid * 16;

    const __nv_bfloat16* Qg = g_Qh + ((size_t)bh * Lv + qb * 128) * HDv;
    const __nv_bfloat16* Kg = g_Kh + (size_t)bh * Lv * HDv;
    const __half*        Vg = g_Vh + (size_t)bh * Lv * HDv;

    const int ld_row  = tid >> 1;
    const int ld_colb = (tid & 1) * 64;

    // Q: 128 rows -> QP region
    {
        const __nv_bfloat16* qs = Qg + (size_t)ld_row * HDv + ld_colb / 2;
        const unsigned qd = sbase + (unsigned)(ld_row * FQS) * 2 + ld_colb;
#pragma unroll
        for (int u = 0; u < 4; u++) cp_async16(qd + u * 16, qs + u * 8);
    }
    auto load_kv = [&](int kb, int stg) {
        const void* src = (ld_row < 64)
            ? (const void*)(Kg + (size_t)(kb * 64 + ld_row) * HDv + ld_colb / 2)
            : (const void*)(Vg + (size_t)(kb * 64 + ld_row - 64) * HDv + ld_colb / 2);
        const unsigned dst = sbase + (unsigned)(KV_OFF + stg * STG_EL + ld_row * FQS) * 2 + ld_colb;
#pragma unroll
        for (int u = 0; u < 4; u++) cp_async16(dst + u * 16, (const char*)src + u * 16);
    };

    load_kv(0, 0);
    cp_commit();
    cp_wait<0>();
    __syncthreads();

    // hoist Q fragments
    const int a_row = lane & 15;
    const int a_k8  = (lane >> 4) << 3;
    const unsigned qA = sbase + (unsigned)((qw + a_row) * FQS + a_k8) * 2;
    unsigned qf[4][4];
#pragma unroll
    for (int kc = 0; kc < 4; kc++)
        ldsm4(qf[kc][0], qf[kc][1], qf[kc][2], qf[kc][3], qA + kc * 32);
    __syncthreads();

    const int b_row = ((lane >> 4) << 3) + (lane & 7);
    const int b_k8  = ((lane >> 3) & 1) << 3;
    const int v_row = (((lane >> 3) & 1) << 3) + (lane & 7);
    const int v_col = (lane >> 4) << 3;
    const unsigned pA = qA;

    float m0 = -1e30f, m1 = -1e30f, l0 = 0.f, l1 = 0.f;
    float o[8][4];
#pragma unroll
    for (int j = 0; j < 8; j++)
#pragma unroll
        for (int r = 0; r < 4; r++) o[j][r] = 0.f;

    const int NT = Lv / 64;
    for (int kb = 0; kb < NT; kb++) {
        const int stg = kb & 1;
        if (kb + 1 < NT) load_kv(kb + 1, stg ^ 1);
        cp_commit();
        cp_wait<1>();
        __syncthreads();

        const unsigned kB = sbase + (unsigned)(KV_OFF + stg * STG_EL + b_row * FQS + b_k8) * 2;
        const unsigned vB = sbase + (unsigned)(KV_OFF + stg * STG_EL + 64 * FQS + v_row * FQS + v_col) * 2;

        // ---- S = Q K^T (bf16) ----
        float s[8][4];
#pragma unroll
        for (int j = 0; j < 8; j++)
#pragma unroll
            for (int r = 0; r < 4; r++) s[j][r] = 0.f;

#pragma unroll
        for (int kc = 0; kc < 4; kc++) {
#pragma unroll
            for (int jp = 0; jp < 4; jp++) {
                unsigned b0, b1, b2, b3;
                ldsm4(b0, b1, b2, b3, kB + (unsigned)(jp * 16 * FQS + kc * 16) * 2);
                mma_bf16(s[2 * jp],     qf[kc][0], qf[kc][1], qf[kc][2], qf[kc][3], b0, b1);
                mma_bf16(s[2 * jp + 1], qf[kc][0], qf[kc][1], qf[kc][2], qf[kc][3], b2, b3);
            }
        }

        // ---- online softmax: f16x2 exp, P stored fp16 ----
        float rmax0 = -1e30f, rmax1 = -1e30f;
#pragma unroll
        for (int j = 0; j < 8; j++) {
            rmax0 = fmaxf(rmax0, fmaxf(s[j][0], s[j][1]));
            rmax1 = fmaxf(rmax1, fmaxf(s[j][2], s[j][3]));
        }
#pragma unroll
        for (int off = 1; off <= 2; off <<= 1) {
            rmax0 = fmaxf(rmax0, __shfl_xor_sync(0xffffffffu, rmax0, off));
            rmax1 = fmaxf(rmax1, __shfl_xor_sync(0xffffffffu, rmax1, off));
        }
        const float mn0 = fmaxf(m0, rmax0);
        const float mn1 = fmaxf(m1, rmax1);
        const float cr0 = ex2(m0 - mn0);
        const float cr1 = ex2(m1 - mn1);
        m0 = mn0; m1 = mn1;

#pragma unroll
        for (int j = 0; j < 8; j++) {
            *(unsigned*)&fsm[(qw + g) * FQS + j * 8 + 2 * t]     = exp2_f16x2(s[j][0], s[j][1], mn0);
            *(unsigned*)&fsm[(qw + 8 + g) * FQS + j * 8 + 2 * t] = exp2_f16x2(s[j][2], s[j][3], mn1);
        }
#pragma unroll
        for (int j = 0; j < 8; j++) {
            o[j][0] *= cr0; o[j][1] *= cr0;
            o[j][2] *= cr1; o[j][3] *= cr1;
        }
        __syncwarp();

        // ---- O += P V (f16), row-sum via ones-mma ----
        float lsum[4] = {0.f, 0.f, 0.f, 0.f};
#pragma unroll
        for (int kc = 0; kc < 4; kc++) {
            unsigned pa0, pa1, pa2, pa3;
            ldsm4(pa0, pa1, pa2, pa3, pA + kc * 32);
            mma_f16(lsum, pa0, pa1, pa2, pa3, ONES_F16X2, ONES_F16X2);
#pragma unroll
            for (int jp = 0; jp < 4; jp++) {
                unsigned b0, b1, b2, b3;
                ldsm4t(b0, b1, b2, b3, vB + (unsigned)(kc * 16 * FQS + jp * 16) * 2);
                mma_f16(o[2 * jp],     pa0, pa1, pa2, pa3, b0, b1);
                mma_f16(o[2 * jp + 1], pa0, pa1, pa2, pa3, b2, b3);
            }
        }
        l0 = l0 * cr0 + lsum[0];
        l1 = l1 * cr1 + lsum[2];
        __syncthreads();
    }

    // ---- write O to g_Oh [B,L,D] in bf16 ----
    const int b = bh >> 4, h = bh & 15;
    const float inv0 = 1.f / l0;
    const float inv1 = 1.f / l1;
    const int q0 = qb * 128 + qw + g;
    const int q1 = q0 + 8;
#pragma unroll
    for (int j = 0; j < 8; j++) {
        const int colD = h * HDv + j * 8 + 2 * t;
        *(__nv_bfloat162*)&g_Oh[((size_t)b * Lv + q0) * Dv + colD] =
            __float22bfloat162_rn(make_float2(o[j][0] * inv0, o[j][1] * inv0));
        *(__nv_bfloat162*)&g_Oh[((size_t)b * Lv + q1) * Dv + colD] =
            __float22bfloat162_rn(make_float2(o[j][2] * inv1, o[j][3] * inv1));
    }
}

// ---------------- LayerNorm: one WARP per row (no block barriers) ----------------
__global__ __launch_bounds__(256)
void layernorm_kernel(const float* __restrict__ gamma,
                      const float* __restrict__ beta,
                      float* __restrict__ out)
{
    const int row  = blockIdx.x * 8 + (threadIdx.x >> 5);
    const int lane = threadIdx.x & 31;
    const float4* y4 = (const float4*)(g_Y + (size_t)row * Dv);

    float4 v[8];
    float sum = 0.f;
#pragma unroll
    for (int i = 0; i < 8; i++) {
        v[i] = y4[lane + i * 32];
        sum += v[i].x + v[i].y + v[i].z + v[i].w;
    }
#pragma unroll
    for (int off = 16; off > 0; off >>= 1)
        sum += __shfl_xor_sync(0xffffffffu, sum, off);
    const float mu = sum * (1.f / Dv);

    float d2 = 0.f;
#pragma unroll
    for (int i = 0; i < 8; i++) {
        float a = v[i].x - mu, b = v[i].y - mu, c = v[i].z - mu, d = v[i].w - mu;
        d2 += a * a + b * b + c * c + d * d;
    }
#pragma unroll
    for (int off = 16; off > 0; off >>= 1)
        d2 += __shfl_xor_sync(0xffffffffu, d2, off);
    const float rs = rsqrtf(d2 * (1.f / Dv) + EPSv);

    float4* o4 = (float4*)(out + (size_t)row * Dv);
    const float4* g4 = (const float4*)gamma;
    const float4* b4 = (const float4*)beta;
#pragma unroll
    for (int i = 0; i < 8; i++) {
        const int c = lane + i * 32;
        float4 gm = g4[c], bt = b4[c];
        float4 r;
        r.x = (v[i].x - mu) * rs * gm.x + bt.x;
        r.y = (v[i].y - mu) * rs * gm.y + bt.y;
        r.z = (v[i].z - mu) * rs * gm.z + bt.z;
        r.w = (v[i].w - mu) * rs * gm.w + bt.w;
        o4[c] = r;
    }
}

// ---------------- launch ----------------
extern "C" void kernel_launch(void* const* d_in, const int* in_sizes, int n_in,
                              void* d_out, int out_size)
{
    (void)in_sizes; (void)n_in; (void)out_size;
    const float* x     = (const float*)d_in[0];
    const float* Wq    = (const float*)d_in[1];
    const float* bq    = (const float*)d_in[2];
    const float* Wk    = (const float*)d_in[3];
    const float* bk    = (const float*)d_in[4];
    const float* Wv    = (const float*)d_in[5];
    const float* bv    = (const float*)d_in[6];
    const float* Wo    = (const float*)d_in[7];
    const float* bo    = (const float*)d_in[8];
    const float* gamma = (const float*)d_in[9];
    const float* beta  = (const float*)d_in[10];
    float* out = (float*)d_out;

    cudaFuncSetAttribute(flash_tc_kernel,
                         cudaFuncAttributeMaxDynamicSharedMemorySize, FLASH_SMEM);
    cudaFuncSetAttribute(gemm_tc_kernel,
                         cudaFuncAttributeMaxDynamicSharedMemorySize, GEMM_SMEM);

    __nv_bfloat16* d_xh = nullptr;
    __nv_bfloat16* d_Wh = nullptr;
    cudaGetSymbolAddress((void**)&d_xh, g_xh);
    cudaGetSymbolAddress((void**)&d_Wh, g_Wh);

    // pre-pass: fp32 -> bf16 (x separate; all 4 W's in one launch)
    const int nx4 = Mv * Dv / 4;
    const int nw4 = Dv * Dv / 4;
    bf16_cvt_x_kernel<<<(nx4 + 255) / 256, 256>>>(x, d_xh, nx4);
    bf16_cvt_kernel<<<dim3((nw4 + 255) / 256, 4), 256>>>(Wq, Wk, Wv, Wo, d_Wh, nw4);

    // fused QKV projection
    gemm_tc_kernel<<<dim3(24, Mv / 128), 256, GEMM_SMEM>>>(0, bq, bk, bv, nullptr, nullptr);

    // attention
    flash_tc_kernel<<<dim3(Lv / 128, Bv * Hv), 256, FLASH_SMEM>>>();

    // output projection + residual
    gemm_tc_kernel<<<dim3(8, Mv / 128), 256, GEMM_SMEM>>>(1, nullptr, nullptr, nullptr, bo, x);

    layernorm_kernel<<<Mv / 8, 256>>>(gamma, beta, out);
}

// round 14
// speedup vs baseline: 2.3681x; 1.0589x over previous
#include <cuda_runtime.h>
#include <cuda_bf16.h>
#include <cuda_fp16.h>
#include <math.h>

// Problem constants
#define Bv 4
#define Lv 2048
#define Dv 1024
#define Hv 16
#define HDv 64
#define Mv (Bv * Lv)          // 8192 rows
#define EPSv 1e-5f

// ---------------- scratch (device globals; no allocs allowed) ----------------
__device__ __nv_bfloat16 g_xh[Mv * Dv];             // x in bf16
__device__ __nv_bfloat16 g_Wh[4 * Dv * Dv];         // Wq,Wk,Wv,Wo in bf16
__device__ __nv_bfloat16 g_Qh[Bv * Hv * Lv * HDv];  // [B,H,L,HD], pre-scaled
__device__ __nv_bfloat16 g_Kh[Bv * Hv * Lv * HDv];
__device__ __half        g_Vh[Bv * Hv * Lv * HDv];  // V in fp16 (PV mma is f16)
__device__ __nv_bfloat16 g_Oh[Mv * Dv];             // attention out, bf16 [B,L,D]
__device__ float g_Y[Mv * Dv];                      // pre-LN residual sum

// ---------------- helpers ----------------
__device__ __forceinline__ float ex2(float x) {
    float y;
    asm("ex2.approx.ftz.f32 %0, %1;" : "=f"(y) : "f"(x));
    return y;
}

__device__ __forceinline__ unsigned smem_u32(const void* p) {
    return (unsigned)__cvta_generic_to_shared(p);
}

__device__ __forceinline__ void cp_async16(unsigned dst, const void* src) {
    asm volatile("cp.async.cg.shared.global [%0], [%1], 16;" :: "r"(dst), "l"(src));
}
__device__ __forceinline__ void cp_commit() {
    asm volatile("cp.async.commit_group;");
}
template<int N> __device__ __forceinline__ void cp_wait() {
    asm volatile("cp.async.wait_group %0;" :: "n"(N));
}

__device__ __forceinline__ void mma_bf16(float* c, unsigned a0, unsigned a1, unsigned a2, unsigned a3,
                                         unsigned b0, unsigned b1) {
    asm volatile(
        "mma.sync.aligned.m16n8k16.row.col.f32.bf16.bf16.f32 "
        "{%0,%1,%2,%3}, {%4,%5,%6,%7}, {%8,%9}, {%0,%1,%2,%3};"
        : "+f"(c[0]), "+f"(c[1]), "+f"(c[2]), "+f"(c[3])
        : "r"(a0), "r"(a1), "r"(a2), "r"(a3), "r"(b0), "r"(b1));
}

__device__ __forceinline__ void mma_f16(float* c, unsigned a0, unsigned a1, unsigned a2, unsigned a3,
                                        unsigned b0, unsigned b1) {
    asm volatile(
        "mma.sync.aligned.m16n8k16.row.col.f32.f16.f16.f32 "
        "{%0,%1,%2,%3}, {%4,%5,%6,%7}, {%8,%9}, {%0,%1,%2,%3};"
        : "+f"(c[0]), "+f"(c[1]), "+f"(c[2]), "+f"(c[3])
        : "r"(a0), "r"(a1), "r"(a2), "r"(a3), "r"(b0), "r"(b1));
}

__device__ __forceinline__ void ldsm4(unsigned& r0, unsigned& r1, unsigned& r2, unsigned& r3, unsigned addr) {
    asm volatile("ldmatrix.sync.aligned.m8n8.x4.shared.b16 {%0,%1,%2,%3}, [%4];"
                 : "=r"(r0), "=r"(r1), "=r"(r2), "=r"(r3) : "r"(addr));
}
__device__ __forceinline__ void ldsm4t(unsigned& r0, unsigned& r1, unsigned& r2, unsigned& r3, unsigned addr) {
    asm volatile("ldmatrix.sync.aligned.m8n8.x4.trans.shared.b16 {%0,%1,%2,%3}, [%4];"
                 : "=r"(r0), "=r"(r1), "=r"(r2), "=r"(r3) : "r"(addr));
}

// pack exp2(a - m), exp2(b - m) into one f16x2 via one MUFU (lo = a-m, hi = b-m)
__device__ __forceinline__ unsigned exp2_f16x2(float a, float b, float m) {
    unsigned r;
    asm("cvt.rn.f16x2.f32 %0, %1, %2;" : "=r"(r) : "f"(b - m), "f"(a - m));
    asm("ex2.approx.f16x2 %0, %0;" : "+r"(r));
    return r;
}

// ---------------- pre-pass: fp32 -> bf16 ----------------
__global__ __launch_bounds__(256)
void bf16_cvt_kernel(const float* __restrict__ s0, const float* __restrict__ s1,
                     const float* __restrict__ s2, const float* __restrict__ s3,
                     __nv_bfloat16* __restrict__ dst, int n4)
{
    const int i = blockIdx.x * 256 + threadIdx.x;
    const float* src = (blockIdx.y == 0) ? s0 : ((blockIdx.y == 1) ? s1 : ((blockIdx.y == 2) ? s2 : s3));
    if (i < n4 && src) {
        float4 v = ((const float4*)src)[i];
        __nv_bfloat162 lo = __float22bfloat162_rn(make_float2(v.x, v.y));
        __nv_bfloat162 hi = __float22bfloat162_rn(make_float2(v.z, v.w));
        uint2 pack;
        pack.x = *(unsigned*)&lo;
        pack.y = *(unsigned*)&hi;
        ((uint2*)(dst + (size_t)blockIdx.y * Dv * Dv))[i] = pack;
    }
}

__global__ __launch_bounds__(256)
void bf16_cvt_x_kernel(const float* __restrict__ src, __nv_bfloat16* __restrict__ dst, int n4)
{
    const int i = blockIdx.x * 256 + threadIdx.x;
    if (i < n4) {
        float4 v = ((const float4*)src)[i];
        __nv_bfloat162 lo = __float22bfloat162_rn(make_float2(v.x, v.y));
        __nv_bfloat162 hi = __float22bfloat162_rn(make_float2(v.z, v.w));
        uint2 pack;
        pack.x = *(unsigned*)&lo;
        pack.y = *(unsigned*)&hi;
        ((uint2*)dst)[i] = pack;
    }
}

// ---------------- bf16 tensor-core GEMM, 3-stage cp.async pipeline ----------------
// mode 0: fused QKV. grid (24, 64). A = g_xh, W = g_Wh[wsel], out Q/K bf16, V fp16.
// mode 1: Wo.        grid (8, 64).  A = g_Oh, W = g_Wh[3], out g_Y fp32 (+residual x).
#define GSTAGES 3
#define ASTR 40
#define BSTR 136
#define A_STAGE (128 * ASTR)
#define B_STAGE (32 * BSTR)
#define GEMM_SMEM (GSTAGES * (A_STAGE + B_STAGE) * 2)   // 56832 B

__global__ __launch_bounds__(256, 2)
void gemm_tc_kernel(int mode,
                    const float* __restrict__ bq, const float* __restrict__ bk,
                    const float* __restrict__ bv, const float* __restrict__ bo,
                    const float* __restrict__ xres)
{
    extern __shared__ __nv_bfloat16 gsm[];
    __nv_bfloat16* sA = gsm;
    __nv_bfloat16* sB = gsm + GSTAGES * A_STAGE;

    const __nv_bfloat16* A;
    const __nv_bfloat16* W;
    const float* bias;
    int wsel, bcol;
    if (mode == 0) {
        wsel = blockIdx.x >> 3;
        bcol = blockIdx.x & 7;
        A = g_xh;
        W = g_Wh + (size_t)wsel * Dv * Dv;
        bias = (wsel == 0) ? bq : ((wsel == 1) ? bk : bv);
    } else {
        wsel = 3;
        bcol = blockIdx.x;
        A = g_Oh;
        W = g_Wh + (size_t)3 * Dv * Dv;
        bias = bo;
    }

    const int tid  = threadIdx.x;
    const int brow = blockIdx.y;
    const int wid  = tid >> 5;
    const int lane = tid & 31;
    const int wm   = wid & 1;
    const int wn   = wid >> 1;
    const int row4 = lane >> 2;
    const int col  = lane & 3;

    const int ac0_row = tid >> 2,          ac_kc = (tid & 3) * 8;
    const int ac1_row = (tid + 256) >> 2;
    const int bc0_row = tid >> 4,          bc_nc = (tid & 15) * 8;
    const int bc1_row = (tid + 256) >> 4;

    const __nv_bfloat16* Agb = A + (size_t)(brow * 128) * Dv;
    const __nv_bfloat16* Wgb = W + bcol * 128;

    float acc[4][4][4];
#pragma unroll
    for (int i = 0; i < 4; i++)
#pragma unroll
        for (int j = 0; j < 4; j++)
#pragma unroll
            for (int r = 0; r < 4; r++) acc[i][j][r] = 0.f;

    auto copy_stage = [&](int s, int k0) {
        __nv_bfloat16* as = sA + s * A_STAGE;
        __nv_bfloat16* bs = sB + s * B_STAGE;
        cp_async16(smem_u32(as + ac0_row * ASTR + ac_kc),
                   Agb + (size_t)ac0_row * Dv + k0 + ac_kc);
        cp_async16(smem_u32(as + ac1_row * ASTR + ac_kc),
                   Agb + (size_t)ac1_row * Dv + k0 + ac_kc);
        cp_async16(smem_u32(bs + bc0_row * BSTR + bc_nc),
                   Wgb + (size_t)(k0 + bc0_row) * Dv + bc_nc);
        cp_async16(smem_u32(bs + bc1_row * BSTR + bc_nc),
                   Wgb + (size_t)(k0 + bc1_row) * Dv + bc_nc);
    };

    const int NK = Dv / 32;
#pragma unroll
    for (int s = 0; s < GSTAGES - 1; s++) {
        copy_stage(s, s * 32);
        cp_commit();
    }

    int stg_c = 0;
    int stg_l = GSTAGES - 1;
    for (int kt = 0; kt < NK; kt++) {
        cp_wait<GSTAGES - 2>();
        __syncthreads();

        const int nxt = kt + GSTAGES - 1;
        if (nxt < NK) copy_stage(stg_l, nxt * 32);
        cp_commit();

        const __nv_bfloat16* as = sA + stg_c * A_STAGE;
        const __nv_bfloat16* bs = sB + stg_c * B_STAGE;

        const unsigned aB = smem_u32(as) +
            (unsigned)((wm * 64 + (lane & 15)) * ASTR + ((lane >> 4) << 3)) * 2;
        const unsigned bB = smem_u32(bs) +
            (unsigned)(((((lane >> 3) & 1) << 3) + (lane & 7)) * BSTR +
                       wn * 32 + ((lane >> 4) << 3)) * 2;

#pragma unroll
        for (int kc = 0; kc < 2; kc++) {
            unsigned af[4][4];
#pragma unroll
            for (int i = 0; i < 4; i++)
                ldsm4(af[i][0], af[i][1], af[i][2], af[i][3],
                      aB + (unsigned)(i * 16 * ASTR + kc * 16) * 2);
#pragma unroll
            for (int jp = 0; jp < 2; jp++) {
                unsigned b0, b1, b2, b3;
                ldsm4t(b0, b1, b2, b3, bB + (unsigned)(kc * 16 * BSTR + jp * 16) * 2);
#pragma unroll
                for (int i = 0; i < 4; i++) {
                    mma_bf16(acc[i][2 * jp],     af[i][0], af[i][1], af[i][2], af[i][3], b0, b1);
                    mma_bf16(acc[i][2 * jp + 1], af[i][0], af[i][1], af[i][2], af[i][3], b2, b3);
                }
            }
        }
        __syncthreads();
        stg_c = (stg_c == GSTAGES - 1) ? 0 : stg_c + 1;
        stg_l = (stg_l == GSTAGES - 1) ? 0 : stg_l + 1;
    }

    // epilogue
    const float qsc = 0.125f * 1.4426950408889634f;
#pragma unroll
    for (int i = 0; i < 4; i++) {
#pragma unroll
        for (int j = 0; j < 4; j++) {
            const int m_lo = brow * 128 + wm * 64 + i * 16 + row4;
            const int n0   = bcol * 128 + wn * 32 + j * 8 + col * 2;
#pragma unroll
            for (int half = 0; half < 2; half++) {
                const int m = m_lo + half * 8;
                float v0 = acc[i][j][half * 2 + 0] + bias[n0];
                float v1 = acc[i][j][half * 2 + 1] + bias[n0 + 1];
                if (mode == 1) {
                    v0 += xres[(size_t)m * Dv + n0];
                    v1 += xres[(size_t)m * Dv + n0 + 1];
                    *(float2*)&g_Y[(size_t)m * Dv + n0] = make_float2(v0, v1);
                } else {
                    const int b = m >> 11, l = m & 2047;
                    const int h = n0 >> 6, hd = n0 & 63;
                    const size_t idx = ((((size_t)b * Hv + h) * Lv) + l) * HDv + hd;
                    if (wsel == 2) {
                        *(__half2*)&g_Vh[idx] = __float22half2_rn(make_float2(v0, v1));
                    } else {
                        if (wsel == 0) { v0 *= qsc; v1 *= qsc; }
                        __nv_bfloat16* dst = (wsel == 0) ? g_Qh : g_Kh;
                        *(__nv_bfloat162*)&dst[idx] = __float22bfloat162_rn(make_float2(v0, v1));
                    }
                }
            }
        }
    }
}

// ---------------- flash attention: FA2 register-P, 3-stage KV ring ----------------
// 256 thr / 8 warps, Br=128, Bc=64, warp M=16. Q hoisted to registers.
// P lives entirely in registers: S C-fragments -> exp -> f16x2 A-fragments for PV.
// smem: 3 stages x (K[64][72] + V[64][72]) bf16/f16. One __syncthreads per tile.
#define FQS 72
#define STG_EL (128 * FQS)
#define FLASH_SMEM (3 * STG_EL * 2)   // 55296 B
#define ONES_F16X2 0x3C003C00u

__global__ __launch_bounds__(256, 2)
void flash_tc_kernel()
{
    extern __shared__ __nv_bfloat16 fsm[];
    const unsigned sbase = smem_u32(fsm);

    const int tid  = threadIdx.x;
    const int bh   = blockIdx.y;
    const int qb   = blockIdx.x;
    const int wid  = tid >> 5;
    const int lane = tid & 31;
    const int qw   = wid * 16;
    const int g    = lane >> 2;
    const int t    = lane & 3;

    const __nv_bfloat16* Qg = g_Qh + ((size_t)bh * Lv + qb * 128) * HDv;
    const __nv_bfloat16* Kg = g_Kh + (size_t)bh * Lv * HDv;
    const __half*        Vg = g_Vh + (size_t)bh * Lv * HDv;

    const int ld_row  = tid >> 1;
    const int ld_colb = (tid & 1) * 64;

    auto load_kv = [&](int kb, int stg) {
        const void* src = (ld_row < 64)
            ? (const void*)(Kg + (size_t)(kb * 64 + ld_row) * HDv + ld_colb / 2)
            : (const void*)(Vg + (size_t)(kb * 64 + ld_row - 64) * HDv + ld_colb / 2);
        const unsigned dst = sbase + (unsigned)(stg * STG_EL + ld_row * FQS) * 2 + ld_colb;
#pragma unroll
        for (int u = 0; u < 4; u++) cp_async16(dst + u * 16, (const char*)src + u * 16);
    };

    // prologue: Q into stage-2 region; KV tiles 0,1 into stages 0,1
    {
        const __nv_bfloat16* qs = Qg + (size_t)ld_row * HDv + ld_colb / 2;
        const unsigned qd = sbase + (unsigned)(2 * STG_EL + ld_row * FQS) * 2 + ld_colb;
#pragma unroll
        for (int u = 0; u < 4; u++) cp_async16(qd + u * 16, qs + u * 8);
        load_kv(0, 0);
        cp_commit();          // group 0 = {Q, kv0}
        load_kv(1, 1);
        cp_commit();          // group 1 = {kv1}
    }
    cp_wait<1>();             // group 0 done: Q + kv0 in smem
    __syncthreads();

    // hoist Q fragments from stage-2 region
    const int a_row = lane & 15;
    const int a_k8  = (lane >> 4) << 3;
    unsigned qf[4][4];
    {
        const unsigned qA = sbase + (unsigned)(2 * STG_EL + (qw + a_row) * FQS + a_k8) * 2;
#pragma unroll
        for (int kc = 0; kc < 4; kc++)
            ldsm4(qf[kc][0], qf[kc][1], qf[kc][2], qf[kc][3], qA + kc * 32);
    }

    const int b_row = ((lane >> 4) << 3) + (lane & 7);
    const int b_k8  = ((lane >> 3) & 1) << 3;
    const int v_row = (((lane >> 3) & 1) << 3) + (lane & 7);
    const int v_col = (lane >> 4) << 3;

    float m0 = -1e30f, m1 = -1e30f, l0 = 0.f, l1 = 0.f;
    float o[8][4];
#pragma unroll
    for (int j = 0; j < 8; j++)
#pragma unroll
        for (int r = 0; r < 4; r++) o[j][r] = 0.f;

    const int NT = Lv / 64;   // 32
    int stg = 0;              // compute stage (kb % 3)
    int stg_l = 2;            // load stage ((kb+2) % 3)
    for (int kb = 0; kb < NT; kb++) {
        cp_wait<1>();         // data for tile kb resident
        __syncthreads();      // visible to all warps; stage stg_l fully read by all

        if (kb + 2 < NT) load_kv(kb + 2, stg_l);
        cp_commit();          // keep group accounting uniform (empty groups ok)

        const unsigned kB = sbase + (unsigned)(stg * STG_EL + b_row * FQS + b_k8) * 2;
        const unsigned vB = sbase + (unsigned)(stg * STG_EL + 64 * FQS + v_row * FQS + v_col) * 2;

        // ---- S = Q K^T (bf16) ----
        float s[8][4];
#pragma unroll
        for (int j = 0; j < 8; j++)
#pragma unroll
            for (int r = 0; r < 4; r++) s[j][r] = 0.f;

#pragma unroll
        for (int kc = 0; kc < 4; kc++) {
#pragma unroll
            for (int jp = 0; jp < 4; jp++) {
                unsigned b0, b1, b2, b3;
                ldsm4(b0, b1, b2, b3, kB + (unsigned)(jp * 16 * FQS + kc * 16) * 2);
                mma_bf16(s[2 * jp],     qf[kc][0], qf[kc][1], qf[kc][2], qf[kc][3], b0, b1);
                mma_bf16(s[2 * jp + 1], qf[kc][0], qf[kc][1], qf[kc][2], qf[kc][3], b2, b3);
            }
        }

        // ---- online softmax (log2 domain), P built in registers ----
        float rmax0 = -1e30f, rmax1 = -1e30f;
#pragma unroll
        for (int j = 0; j < 8; j++) {
            rmax0 = fmaxf(rmax0, fmaxf(s[j][0], s[j][1]));
            rmax1 = fmaxf(rmax1, fmaxf(s[j][2], s[j][3]));
        }
#pragma unroll
        for (int off = 1; off <= 2; off <<= 1) {
            rmax0 = fmaxf(rmax0, __shfl_xor_sync(0xffffffffu, rmax0, off));
            rmax1 = fmaxf(rmax1, __shfl_xor_sync(0xffffffffu, rmax1, off));
        }
        const float mn0 = fmaxf(m0, rmax0);
        const float mn1 = fmaxf(m1, rmax1);
        const float cr0 = ex2(m0 - mn0);
        const float cr1 = ex2(m1 - mn1);
        m0 = mn0; m1 = mn1;

#pragma unroll
        for (int j = 0; j < 8; j++) {
            o[j][0] *= cr0; o[j][1] *= cr0;
            o[j][2] *= cr1; o[j][3] *= cr1;
        }

        // ---- O += P V (f16), P as register A-fragments; row-sum via ones-mma ----
        float lsum[4] = {0.f, 0.f, 0.f, 0.f};
#pragma unroll
        for (int kc = 0; kc < 4; kc++) {
            // A-frag for kv-chunk [16kc, 16kc+16):
            // a0: row g,   k=2t..2t+1   -> S tile j=2kc,   c0/c1 (max mn0)
            // a1: row g+8, k=2t..2t+1   -> S tile j=2kc,   c2/c3 (max mn1)
            // a2: row g,   k=2t+8..+9   -> S tile j=2kc+1, c0/c1 (max mn0)
            // a3: row g+8, k=2t+8..+9   -> S tile j=2kc+1, c2/c3 (max mn1)
            const unsigned pa0 = exp2_f16x2(s[2 * kc][0],     s[2 * kc][1],     mn0);
            const unsigned pa1 = exp2_f16x2(s[2 * kc][2],     s[2 * kc][3],     mn1);
            const unsigned pa2 = exp2_f16x2(s[2 * kc + 1][0], s[2 * kc + 1][1], mn0);
            const unsigned pa3 = exp2_f16x2(s[2 * kc + 1][2], s[2 * kc + 1][3], mn1);
            mma_f16(lsum, pa0, pa1, pa2, pa3, ONES_F16X2, ONES_F16X2);
#pragma unroll
            for (int jp = 0; jp < 4; jp++) {
                unsigned b0, b1, b2, b3;
                ldsm4t(b0, b1, b2, b3, vB + (unsigned)(kc * 16 * FQS + jp * 16) * 2);
                mma_f16(o[2 * jp],     pa0, pa1, pa2, pa3, b0, b1);
                mma_f16(o[2 * jp + 1], pa0, pa1, pa2, pa3, b2, b3);
            }
        }
        l0 = l0 * cr0 + lsum[0];
        l1 = l1 * cr1 + lsum[2];

        stg   = (stg   == 2) ? 0 : stg + 1;
        stg_l = (stg_l == 2) ? 0 : stg_l + 1;
    }

    // ---- write O to g_Oh [B,L,D] in bf16 ----
    const int b = bh >> 4, h = bh & 15;
    const float inv0 = 1.f / l0;
    const float inv1 = 1.f / l1;
    const int q0 = qb * 128 + qw + g;
    const int q1 = q0 + 8;
#pragma unroll
    for (int j = 0; j < 8; j++) {
        const int colD = h * HDv + j * 8 + 2 * t;
        *(__nv_bfloat162*)&g_Oh[((size_t)b * Lv + q0) * Dv + colD] =
            __float22bfloat162_rn(make_float2(o[j][0] * inv0, o[j][1] * inv0));
        *(__nv_bfloat162*)&g_Oh[((size_t)b * Lv + q1) * Dv + colD] =
            __float22bfloat162_rn(make_float2(o[j][2] * inv1, o[j][3] * inv1));
    }
}

// ---------------- LayerNorm: one WARP per row ----------------
__global__ __launch_bounds__(256)
void layernorm_kernel(const float* __restrict__ gamma,
                      const float* __restrict__ beta,
                      float* __restrict__ out)
{
    const int row  = blockIdx.x * 8 + (threadIdx.x >> 5);
    const int lane = threadIdx.x & 31;
    const float4* y4 = (const float4*)(g_Y + (size_t)row * Dv);

    float4 v[8];
    float sum = 0.f;
#pragma unroll
    for (int i = 0; i < 8; i++) {
        v[i] = y4[lane + i * 32];
        sum += v[i].x + v[i].y + v[i].z + v[i].w;
    }
#pragma unroll
    for (int off = 16; off > 0; off >>= 1)
        sum += __shfl_xor_sync(0xffffffffu, sum, off);
    const float mu = sum * (1.f / Dv);

    float d2 = 0.f;
#pragma unroll
    for (int i = 0; i < 8; i++) {
        float a = v[i].x - mu, b = v[i].y - mu, c = v[i].z - mu, d = v[i].w - mu;
        d2 += a * a + b * b + c * c + d * d;
    }
#pragma unroll
    for (int off = 16; off > 0; off >>= 1)
        d2 += __shfl_xor_sync(0xffffffffu, d2, off);
    const float rs = rsqrtf(d2 * (1.f / Dv) + EPSv);

    float4* o4 = (float4*)(out + (size_t)row * Dv);
    const float4* g4 = (const float4*)gamma;
    const float4* b4 = (const float4*)beta;
#pragma unroll
    for (int i = 0; i < 8; i++) {
        const int c = lane + i * 32;
        float4 gm = g4[c], bt = b4[c];
        float4 r;
        r.x = (v[i].x - mu) * rs * gm.x + bt.x;
        r.y = (v[i].y - mu) * rs * gm.y + bt.y;
        r.z = (v[i].z - mu) * rs * gm.z + bt.z;
        r.w = (v[i].w - mu) * rs * gm.w + bt.w;
        o4[c] = r;
    }
}

// ---------------- launch ----------------
extern "C" void kernel_launch(void* const* d_in, const int* in_sizes, int n_in,
                              void* d_out, int out_size)
{
    (void)in_sizes; (void)n_in; (void)out_size;
    const float* x     = (const float*)d_in[0];
    const float* Wq    = (const float*)d_in[1];
    const float* bq    = (const float*)d_in[2];
    const float* Wk    = (const float*)d_in[3];
    const float* bk    = (const float*)d_in[4];
    const float* Wv    = (const float*)d_in[5];
    const float* bv    = (const float*)d_in[6];
    const float* Wo    = (const float*)d_in[7];
    const float* bo    = (const float*)d_in[8];
    const float* gamma = (const float*)d_in[9];
    const float* beta  = (const float*)d_in[10];
    float* out = (float*)d_out;

    cudaFuncSetAttribute(flash_tc_kernel,
                         cudaFuncAttributeMaxDynamicSharedMemorySize, FLASH_SMEM);
    cudaFuncSetAttribute(gemm_tc_kernel,
                         cudaFuncAttributeMaxDynamicSharedMemorySize, GEMM_SMEM);

    __nv_bfloat16* d_xh = nullptr;
    __nv_bfloat16* d_Wh = nullptr;
    cudaGetSymbolAddress((void**)&d_xh, g_xh);
    cudaGetSymbolAddress((void**)&d_Wh, g_Wh);

    // pre-pass: fp32 -> bf16
    const int nx4 = Mv * Dv / 4;
    const int nw4 = Dv * Dv / 4;
    bf16_cvt_x_kernel<<<(nx4 + 255) / 256, 256>>>(x, d_xh, nx4);
    bf16_cvt_kernel<<<dim3((nw4 + 255) / 256, 4), 256>>>(Wq, Wk, Wv, Wo, d_Wh, nw4);

    // fused QKV projection
    gemm_tc_kernel<<<dim3(24, Mv / 128), 256, GEMM_SMEM>>>(0, bq, bk, bv, nullptr, nullptr);

    // attention
    flash_tc_kernel<<<dim3(Lv / 128, Bv * Hv), 256, FLASH_SMEM>>>();

    // output projection + residual
    gemm_tc_kernel<<<dim3(8, Mv / 128), 256, GEMM_SMEM>>>(1, nullptr, nullptr, nullptr, bo, x);

    layernorm_kernel<<<Mv / 8, 256>>>(gamma, beta, out);
}